// round 9
// baseline (speedup 1.0000x reference)
#include <cuda_runtime.h>
#include <cuda_bf16.h>
#include <cstdint>

#define BATCH 2
#define SEQ   2048
#define EMB   1024
#define HEADS 16
#define HDIM  64
#define MROWS (BATCH*SEQ)   // 4096
#define NQKV  (3*EMB)       // 3072
#define QKVN  (BATCH*HEADS*SEQ*HDIM)

// ---------------- scratch (device globals; no runtime alloc) ----------------
__device__ float g_attn[MROWS*EMB];              // [b,t,(h d)] fp32

__device__ __nv_bfloat16 g_xhi[MROWS*EMB],  g_xlo[MROWS*EMB];
__device__ __nv_bfloat16 g_wqh[NQKV*EMB],   g_wql[NQKV*EMB];
__device__ __nv_bfloat16 g_woh[EMB*EMB],    g_wol[EMB*EMB];
__device__ __nv_bfloat16 g_ahi[MROWS*EMB],  g_alo[MROWS*EMB];

__device__ __nv_bfloat16 g_qh[QKVN], g_ql[QKVN];   // [b,h,t,d]
__device__ __nv_bfloat16 g_kh[QKVN], g_kl[QKVN];   // [b,h,t,d]
__device__ __nv_bfloat16 g_vth[QKVN], g_vtl[QKVN]; // [b,h,d,t]  (transposed)

// ---------------- helpers ----------------
__device__ __forceinline__ uint32_t smem_u32(const void* p) {
    uint32_t a;
    asm("{ .reg .u64 t; cvta.to.shared.u64 t, %1; cvt.u32.u64 %0, t; }" : "=r"(a) : "l"(p));
    return a;
}
__device__ __forceinline__ void cp16(uint32_t s, const void* g) {
    asm volatile("cp.async.cg.shared.global [%0], [%1], 16;" :: "r"(s), "l"(g));
}
#define CP_COMMIT() asm volatile("cp.async.commit_group;" ::: "memory")
#define CP_WAIT0()  asm volatile("cp.async.wait_group 0;" ::: "memory")

__device__ __forceinline__ void ldsm_x4(uint32_t* r, uint32_t addr) {
    asm volatile("ldmatrix.sync.aligned.m8n8.x4.shared.b16 {%0,%1,%2,%3}, [%4];"
        : "=r"(r[0]), "=r"(r[1]), "=r"(r[2]), "=r"(r[3]) : "r"(addr));
}
__device__ __forceinline__ void mma16816(float* d, const uint32_t* a, uint32_t b0, uint32_t b1) {
    asm volatile("mma.sync.aligned.m16n8k16.row.col.f32.bf16.bf16.f32 "
        "{%0,%1,%2,%3}, {%4,%5,%6,%7}, {%8,%9}, {%0,%1,%2,%3};"
        : "+f"(d[0]), "+f"(d[1]), "+f"(d[2]), "+f"(d[3])
        : "r"(a[0]), "r"(a[1]), "r"(a[2]), "r"(a[3]), "r"(b0), "r"(b1));
}
__device__ __forceinline__ uint32_t packsplit(float x, float y, uint32_t& lo) {
    uint32_t hp;
    asm("cvt.rn.bf16x2.f32 %0, %1, %2;" : "=r"(hp) : "f"(y), "f"(x));
    float hx = __uint_as_float(hp << 16);
    float hy = __uint_as_float(hp & 0xffff0000u);
    float lx = x - hx, ly = y - hy;
    asm("cvt.rn.bf16x2.f32 %0, %1, %2;" : "=r"(lo) : "f"(ly), "f"(lx));
    return hp;
}
// fast 2^t on FMA pipe (t <= 0 in all uses); |rel err| ~ 2.4e-6
__device__ __forceinline__ float e2(float t) {
    t = fmaxf(t, -124.0f);
    int i = __float2int_rn(t);
    float f = t - (float)i;
    float p = 1.3333558146e-3f;
    p = fmaf(p, f, 9.6181291076e-3f);
    p = fmaf(p, f, 5.5504108664e-2f);
    p = fmaf(p, f, 2.4022650696e-1f);
    p = fmaf(p, f, 6.9314718056e-1f);
    p = fmaf(p, f, 1.0f);
    return __int_as_float((i << 23) + __float_as_int(p));
}
#define EXPSCALE 11.541560327111707f   // 8 * log2(e)

// ---------------- fp32 -> bf16 hi/lo split ----------------
template<int SEL>
__global__ __launch_bounds__(256) void split_kernel(const float* __restrict__ srcp, int n4) {
    const float* src = (SEL == 3) ? (const float*)g_attn : srcp;
    __nv_bfloat16* hi = (SEL==0) ? g_xhi : (SEL==1) ? g_wqh : (SEL==2) ? g_woh : g_ahi;
    __nv_bfloat16* lo = (SEL==0) ? g_xlo : (SEL==1) ? g_wql : (SEL==2) ? g_wol : g_alo;
    int i = blockIdx.x * 256 + threadIdx.x;
    if (i >= n4) return;
    float4 v = ((const float4*)src)[i];
    __nv_bfloat16 h0 = __float2bfloat16(v.x);
    __nv_bfloat16 h1 = __float2bfloat16(v.y);
    __nv_bfloat16 h2 = __float2bfloat16(v.z);
    __nv_bfloat16 h3 = __float2bfloat16(v.w);
    __nv_bfloat16 l0 = __float2bfloat16(v.x - __bfloat162float(h0));
    __nv_bfloat16 l1 = __float2bfloat16(v.y - __bfloat162float(h1));
    __nv_bfloat16 l2 = __float2bfloat16(v.z - __bfloat162float(h2));
    __nv_bfloat16 l3 = __float2bfloat16(v.w - __bfloat162float(h3));
    ushort4 hv, lv;
    hv.x = *(unsigned short*)&h0; hv.y = *(unsigned short*)&h1;
    hv.z = *(unsigned short*)&h2; hv.w = *(unsigned short*)&h3;
    lv.x = *(unsigned short*)&l0; lv.y = *(unsigned short*)&l1;
    lv.z = *(unsigned short*)&l2; lv.w = *(unsigned short*)&l3;
    ((ushort4*)hi)[i] = hv;
    ((ushort4*)lo)[i] = lv;
}

// ---------------- HMMA GEMM (bf16 split, 3-term), cp.async double-buffered --
// Each thread loads 4 parts x 4 tiles = 16 x 16B per chunk: slot = p*256+tid
// sweeps the FULL 128x64 tile for every tile t (fixes the R5/R6 indexing bug).
#define LDP 72
#define CH_ELEMS  (128*LDP)
#define BUF_ELEMS (4*CH_ELEMS)                 // Ahi, Alo, Bhi, Blo
#define GEMM_SMEM (2*BUF_ELEMS*2)              // 2 buffers, bytes

template<int EPI>
__global__ __launch_bounds__(256) void hmma_gemm(float* __restrict__ Cout) {
    const __nv_bfloat16* base[4] = {
        EPI ? g_ahi : g_xhi, EPI ? g_alo : g_xlo,
        EPI ? g_woh : g_wqh, EPI ? g_wol : g_wql };

    extern __shared__ __nv_bfloat16 sm[];

    int tid = threadIdx.x, lane = tid & 31, wid = tid >> 5;
    int m0 = blockIdx.y * 128, n0 = blockIdx.x * 128;
    int wm = (wid & 3) * 32;
    int wn = (wid >> 2) * 64;

    float acc[2][8][4];
#pragma unroll
    for (int i = 0; i < 2; i++)
#pragma unroll
        for (int j = 0; j < 8; j++)
#pragma unroll
            for (int q = 0; q < 4; q++) acc[i][j][q] = 0.0f;

    uint32_t smb = smem_u32(sm);

    auto load_chunk = [&](int k0, int buf) {
        uint32_t dstb = smb + (uint32_t)(buf * BUF_ELEMS) * 2;
#pragma unroll
        for (int t = 0; t < 4; t++) {
            const __nv_bfloat16* src = base[t];
            int rbase = (t < 2) ? m0 : n0;
#pragma unroll
            for (int p = 0; p < 4; p++) {
                int slot = p * 256 + tid;            // 0..1023 over full tile
                int r = slot >> 3, c = (slot & 7) * 8;
                cp16(dstb + (uint32_t)(t*CH_ELEMS + r*LDP + c) * 2,
                     &src[(size_t)(rbase + r) * EMB + k0 + c]);
            }
        }
    };

    load_chunk(0, 0);
    CP_COMMIT();

    for (int ck = 0; ck < 16; ck++) {
        int buf = ck & 1;
        CP_WAIT0();
        __syncthreads();
        if (ck + 1 < 16) { load_chunk((ck + 1) * 64, buf ^ 1); CP_COMMIT(); }

        uint32_t asb0 = smb + (uint32_t)(buf*BUF_ELEMS + 0*CH_ELEMS) * 2;
        uint32_t asb1 = smb + (uint32_t)(buf*BUF_ELEMS + 1*CH_ELEMS) * 2;
        uint32_t bsb0 = smb + (uint32_t)(buf*BUF_ELEMS + 2*CH_ELEMS) * 2;
        uint32_t bsb1 = smb + (uint32_t)(buf*BUF_ELEMS + 3*CH_ELEMS) * 2;

#pragma unroll
        for (int kc = 0; kc < 64; kc += 16) {
            uint32_t ah[2][4], al[2][4];
#pragma unroll
            for (int mi = 0; mi < 2; mi++) {
                uint32_t off = (uint32_t)((wm + mi*16 + (lane & 15)) * LDP
                                           + kc + (lane >> 4) * 8) * 2;
                ldsm_x4(ah[mi], asb0 + off);
                ldsm_x4(al[mi], asb1 + off);
            }
#pragma unroll
            for (int nj = 0; nj < 4; nj++) {
                uint32_t boff = (uint32_t)((wn + nj*16 + (lane & 7) + ((lane >> 4) & 1) * 8) * LDP
                                           + kc + ((lane >> 3) & 1) * 8) * 2;
                uint32_t bh[4], bl[4];
                ldsm_x4(bh, bsb0 + boff);
                ldsm_x4(bl, bsb1 + boff);
#pragma unroll
                for (int s2 = 0; s2 < 2; s2++) {
#pragma unroll
                    for (int mi = 0; mi < 2; mi++) {
                        float* d = acc[mi][nj*2 + s2];
                        mma16816(d, ah[mi], bh[s2*2], bh[s2*2+1]);
                        mma16816(d, ah[mi], bl[s2*2], bl[s2*2+1]);
                        mma16816(d, al[mi], bh[s2*2], bh[s2*2+1]);
                    }
                }
            }
        }
    }

#pragma unroll
    for (int mi = 0; mi < 2; mi++) {
#pragma unroll
        for (int ni = 0; ni < 8; ni++) {
            float* d = acc[mi][ni];
            int mrow0 = m0 + wm + mi*16 + (lane >> 2);
            int ncol0 = n0 + wn + ni*8 + 2*(lane & 3);
            if (EPI == 0) {
#pragma unroll
                for (int h2 = 0; h2 < 2; h2++) {
                    int m = mrow0 + h2*8;
                    int bb = m >> 11, t = m & 2047;
#pragma unroll
                    for (int c2 = 0; c2 < 2; c2++) {
                        int n  = ncol0 + c2;
                        int di = n / 48;
                        int ki = (n >> 4) % 3;
                        int hh = n & 15;
                        float v = d[h2*2 + c2];
                        __nv_bfloat16 hb = __float2bfloat16(v);
                        __nv_bfloat16 lb = __float2bfloat16(v - __bfloat162float(hb));
                        if (ki == 2) {
                            size_t dst = ((size_t)(bb*HEADS + hh) * HDIM + di) * SEQ + t;
                            g_vth[dst] = hb; g_vtl[dst] = lb;
                        } else {
                            size_t dst = ((size_t)(bb*HEADS + hh) * SEQ + t) * HDIM + di;
                            if (ki == 0) { g_qh[dst] = hb; g_ql[dst] = lb; }
                            else         { g_kh[dst] = hb; g_kl[dst] = lb; }
                        }
                    }
                }
            } else {
                float2 r0; r0.x = d[0]; r0.y = d[1];
                float2 r1; r1.x = d[2]; r1.y = d[3];
                *(float2*)&Cout[(size_t)mrow0       * EMB + ncol0] = r0;
                *(float2*)&Cout[(size_t)(mrow0 + 8) * EMB + ncol0] = r1;
            }
        }
    }
}

// ---------------- HMMA flash attention (R4-proven, unchanged) ----------------
#define ALDP 72
#define ATT_SMEM ((2*128 + 4*64) * ALDP * 2)

__global__ __launch_bounds__(128) void attn_hmma() {
    extern __shared__ __nv_bfloat16 sm[];
    __nv_bfloat16 *Qh = sm,              *Ql = Qh + 128*ALDP;
    __nv_bfloat16 *Kh = Ql + 128*ALDP,   *Kl = Kh + 64*ALDP;
    __nv_bfloat16 *Vh = Kl + 64*ALDP,    *Vl = Vh + 64*ALDP;

    int tid = threadIdx.x, lane = tid & 31, wid = tid >> 5;
    int bh = blockIdx.y, q0 = blockIdx.x * 128;
    int wm = wid * 32;

    size_t qgbase = ((size_t)bh * SEQ + q0) * HDIM;
#pragma unroll
    for (int i = 0; i < 8; i++) {
        int slot = i * 128 + tid;
        int r = slot >> 3, c = (slot & 7) * 8;
        *(uint4*)&Qh[r*ALDP + c] = *(const uint4*)&g_qh[qgbase + (size_t)r*HDIM + c];
        *(uint4*)&Ql[r*ALDP + c] = *(const uint4*)&g_ql[qgbase + (size_t)r*HDIM + c];
    }

    float O[2][8][4];
#pragma unroll
    for (int i = 0; i < 2; i++)
#pragma unroll
        for (int j = 0; j < 8; j++)
#pragma unroll
            for (int q = 0; q < 4; q++) O[i][j][q] = 0.0f;
    float lacc[4] = {0.f, 0.f, 0.f, 0.f};
    float mrun[4] = {-1e30f, -1e30f, -1e30f, -1e30f};

    uint32_t qsbh = smem_u32(Qh), qsbl = smem_u32(Ql);
    uint32_t ksbh = smem_u32(Kh), ksbl = smem_u32(Kl);
    uint32_t vsbh = smem_u32(Vh), vsbl = smem_u32(Vl);

    const size_t kgbase = (size_t)bh * SEQ * HDIM;
    const size_t vgbase = (size_t)bh * HDIM * SEQ;

    for (int kt = 0; kt < SEQ/64; kt++) {
        __syncthreads();
#pragma unroll
        for (int i = 0; i < 4; i++) {
            int slot = i * 128 + tid;
            int r = slot >> 3, c = (slot & 7) * 8;
            *(uint4*)&Kh[r*ALDP + c] = *(const uint4*)&g_kh[kgbase + (size_t)(kt*64 + r)*HDIM + c];
            *(uint4*)&Kl[r*ALDP + c] = *(const uint4*)&g_kl[kgbase + (size_t)(kt*64 + r)*HDIM + c];
            *(uint4*)&Vh[r*ALDP + c] = *(const uint4*)&g_vth[vgbase + (size_t)r*SEQ + kt*64 + c];
            *(uint4*)&Vl[r*ALDP + c] = *(const uint4*)&g_vtl[vgbase + (size_t)r*SEQ + kt*64 + c];
        }
        __syncthreads();

        // ---- S = Q K^T ----
        float S[2][8][4];
#pragma unroll
        for (int i = 0; i < 2; i++)
#pragma unroll
            for (int j = 0; j < 8; j++)
#pragma unroll
                for (int q = 0; q < 4; q++) S[i][j][q] = 0.0f;

#pragma unroll
        for (int ks = 0; ks < 4; ks++) {
            uint32_t qh[2][4], ql[2][4];
#pragma unroll
            for (int mi = 0; mi < 2; mi++) {
                uint32_t off = (uint32_t)((wm + mi*16 + (lane & 15)) * ALDP
                                           + ks*16 + (lane >> 4) * 8) * 2;
                ldsm_x4(qh[mi], qsbh + off);
                ldsm_x4(ql[mi], qsbl + off);
            }
#pragma unroll
            for (int nj = 0; nj < 4; nj++) {
                uint32_t boff = (uint32_t)((nj*16 + (lane & 7) + ((lane >> 4) & 1) * 8) * ALDP
                                           + ks*16 + ((lane >> 3) & 1) * 8) * 2;
                uint32_t kh[4], kl[4];
                ldsm_x4(kh, ksbh + boff);
                ldsm_x4(kl, ksbl + boff);
#pragma unroll
                for (int s2 = 0; s2 < 2; s2++) {
#pragma unroll
                    for (int mi = 0; mi < 2; mi++) {
                        float* d = S[mi][nj*2 + s2];
                        mma16816(d, qh[mi], kh[s2*2], kh[s2*2+1]);
                        mma16816(d, qh[mi], kl[s2*2], kl[s2*2+1]);
                        mma16816(d, ql[mi], kh[s2*2], kh[s2*2+1]);
                    }
                }
            }
        }

        // ---- online softmax ----
        float tmx[4] = {-1e30f, -1e30f, -1e30f, -1e30f};
#pragma unroll
        for (int mi = 0; mi < 2; mi++)
#pragma unroll
            for (int ni = 0; ni < 8; ni++) {
                tmx[mi*2+0] = fmaxf(tmx[mi*2+0], fmaxf(S[mi][ni][0], S[mi][ni][1]));
                tmx[mi*2+1] = fmaxf(tmx[mi*2+1], fmaxf(S[mi][ni][2], S[mi][ni][3]));
            }
#pragma unroll
        for (int i = 0; i < 4; i++) {
            tmx[i] = fmaxf(tmx[i], __shfl_xor_sync(0xffffffffu, tmx[i], 1));
            tmx[i] = fmaxf(tmx[i], __shfl_xor_sync(0xffffffffu, tmx[i], 2));
        }
        float corr[4];
#pragma unroll
        for (int i = 0; i < 4; i++) {
            float mn = fmaxf(mrun[i], tmx[i]);
            corr[i] = e2((mrun[i] - mn) * EXPSCALE);
            mrun[i] = mn;
            lacc[i] *= corr[i];
        }
#pragma unroll
        for (int mi = 0; mi < 2; mi++)
#pragma unroll
            for (int ni = 0; ni < 8; ni++) {
                O[mi][ni][0] *= corr[mi*2+0];
                O[mi][ni][1] *= corr[mi*2+0];
                O[mi][ni][2] *= corr[mi*2+1];
                O[mi][ni][3] *= corr[mi*2+1];
            }
#pragma unroll
        for (int mi = 0; mi < 2; mi++)
#pragma unroll
            for (int ni = 0; ni < 8; ni++) {
                float p0 = e2((S[mi][ni][0] - mrun[mi*2+0]) * EXPSCALE);
                float p1 = e2((S[mi][ni][1] - mrun[mi*2+0]) * EXPSCALE);
                float p2 = e2((S[mi][ni][2] - mrun[mi*2+1]) * EXPSCALE);
                float p3 = e2((S[mi][ni][3] - mrun[mi*2+1]) * EXPSCALE);
                S[mi][ni][0] = p0; S[mi][ni][1] = p1;
                S[mi][ni][2] = p2; S[mi][ni][3] = p3;
                lacc[mi*2+0] += p0 + p1;
                lacc[mi*2+1] += p2 + p3;
            }

        // ---- O += P @ V ----
#pragma unroll
        for (int ks = 0; ks < 4; ks++) {
            uint32_t pah[2][4], pal[2][4];
#pragma unroll
            for (int mi = 0; mi < 2; mi++) {
                pah[mi][0] = packsplit(S[mi][2*ks  ][0], S[mi][2*ks  ][1], pal[mi][0]);
                pah[mi][1] = packsplit(S[mi][2*ks  ][2], S[mi][2*ks  ][3], pal[mi][1]);
                pah[mi][2] = packsplit(S[mi][2*ks+1][0], S[mi][2*ks+1][1], pal[mi][2]);
                pah[mi][3] = packsplit(S[mi][2*ks+1][2], S[mi][2*ks+1][3], pal[mi][3]);
            }
#pragma unroll
            for (int dj = 0; dj < 4; dj++) {
                uint32_t boff = (uint32_t)((dj*16 + (lane & 7) + ((lane >> 4) & 1) * 8) * ALDP
                                           + ks*16 + ((lane >> 3) & 1) * 8) * 2;
                uint32_t vh[4], vl[4];
                ldsm_x4(vh, vsbh + boff);
                ldsm_x4(vl, vsbl + boff);
#pragma unroll
                for (int s2 = 0; s2 < 2; s2++) {
#pragma unroll
                    for (int mi = 0; mi < 2; mi++) {
                        float* d = O[mi][dj*2 + s2];
                        mma16816(d, pah[mi], vh[s2*2], vh[s2*2+1]);
                        mma16816(d, pah[mi], vl[s2*2], vl[s2*2+1]);
                        mma16816(d, pal[mi], vh[s2*2], vh[s2*2+1]);
                    }
                }
            }
        }
    }

    // ---- finalize ----
    float inv[4];
#pragma unroll
    for (int i = 0; i < 4; i++) {
        lacc[i] += __shfl_xor_sync(0xffffffffu, lacc[i], 1);
        lacc[i] += __shfl_xor_sync(0xffffffffu, lacc[i], 2);
        inv[i] = 1.0f / lacc[i];
    }
    int b = bh >> 4, h = bh & 15;
#pragma unroll
    for (int mi = 0; mi < 2; mi++) {
#pragma unroll
        for (int h2 = 0; h2 < 2; h2++) {
            int m = q0 + wm + mi*16 + (lane >> 2) + h2*8;
            float* dst = g_attn + ((size_t)b * SEQ + m) * EMB + h * HDIM;
            float iv = inv[mi*2 + h2];
#pragma unroll
            for (int ni = 0; ni < 8; ni++) {
                float2 r;
                r.x = O[mi][ni][h2*2+0] * iv;
                r.y = O[mi][ni][h2*2+1] * iv;
                *(float2*)&dst[ni*8 + 2*(lane & 3)] = r;
            }
        }
    }
}

// ---------------------------------------------------------------------------
extern "C" void kernel_launch(void* const* d_in, const int* in_sizes, int n_in,
                              void* d_out, int out_size) {
    const float* x     = (const float*)d_in[0];   // [B,T,E]
    const float* w_qkv = (const float*)d_in[1];   // [3E,E]
    const float* w_out = (const float*)d_in[2];   // [E,E]
    float* out = (float*)d_out;                   // [B,T,E]

    cudaFuncSetAttribute(hmma_gemm<0>, cudaFuncAttributeMaxDynamicSharedMemorySize, GEMM_SMEM);
    cudaFuncSetAttribute(hmma_gemm<1>, cudaFuncAttributeMaxDynamicSharedMemorySize, GEMM_SMEM);
    cudaFuncSetAttribute(attn_hmma,    cudaFuncAttributeMaxDynamicSharedMemorySize, ATT_SMEM);

    // 1) split inputs to bf16 hi/lo
    split_kernel<0><<<(MROWS*EMB/4 + 255)/256, 256>>>(x,     MROWS*EMB/4);
    split_kernel<1><<<(NQKV*EMB/4  + 255)/256, 256>>>(w_qkv, NQKV*EMB/4);
    split_kernel<2><<<(EMB*EMB/4   + 255)/256, 256>>>(w_out, EMB*EMB/4);

    // 2) QKV projection (HMMA, cp.async pipelined — corrected tile loads)
    hmma_gemm<0><<<dim3(NQKV/128, MROWS/128), 256, GEMM_SMEM>>>(nullptr);

    // 3) HMMA flash attention (R4-proven)
    attn_hmma<<<dim3(SEQ/128, BATCH*HEADS), 128, ATT_SMEM>>>();

    // 4) split attention output, then output projection (HMMA pipelined)
    split_kernel<3><<<(MROWS*EMB/4 + 255)/256, 256>>>(nullptr, MROWS*EMB/4);
    hmma_gemm<1><<<dim3(EMB/128, MROWS/128), 256, GEMM_SMEM>>>(out);
}

// round 10
// speedup vs baseline: 1.3690x; 1.3690x over previous
#include <cuda_runtime.h>
#include <cuda_bf16.h>
#include <cstdint>

#define BATCH 2
#define SEQ   2048
#define EMB   1024
#define HEADS 16
#define HDIM  64
#define MROWS (BATCH*SEQ)   // 4096
#define NQKV  (3*EMB)       // 3072
#define QKVN  (BATCH*HEADS*SEQ*HDIM)

// ---------------- scratch (device globals; no runtime alloc) ----------------
__device__ float g_attn[MROWS*EMB];              // [b,t,(h d)] fp32

__device__ __nv_bfloat16 g_xhi[MROWS*EMB],  g_xlo[MROWS*EMB];
__device__ __nv_bfloat16 g_wqh[NQKV*EMB],   g_wql[NQKV*EMB];
__device__ __nv_bfloat16 g_woh[EMB*EMB],    g_wol[EMB*EMB];
__device__ __nv_bfloat16 g_ahi[MROWS*EMB],  g_alo[MROWS*EMB];

__device__ __nv_bfloat16 g_qh[QKVN], g_ql[QKVN];   // [b,h,t,d]
__device__ __nv_bfloat16 g_kh[QKVN], g_kl[QKVN];   // [b,h,t,d]
__device__ __nv_bfloat16 g_vth[QKVN], g_vtl[QKVN]; // [b,h,d,t]  (transposed)

// ---------------- helpers ----------------
__device__ __forceinline__ uint32_t smem_u32(const void* p) {
    uint32_t a;
    asm("{ .reg .u64 t; cvta.to.shared.u64 t, %1; cvt.u32.u64 %0, t; }" : "=r"(a) : "l"(p));
    return a;
}
__device__ __forceinline__ void ldsm_x4(uint32_t* r, uint32_t addr) {
    asm volatile("ldmatrix.sync.aligned.m8n8.x4.shared.b16 {%0,%1,%2,%3}, [%4];"
        : "=r"(r[0]), "=r"(r[1]), "=r"(r[2]), "=r"(r[3]) : "r"(addr));
}
__device__ __forceinline__ void mma16816(float* d, const uint32_t* a, uint32_t b0, uint32_t b1) {
    asm volatile("mma.sync.aligned.m16n8k16.row.col.f32.bf16.bf16.f32 "
        "{%0,%1,%2,%3}, {%4,%5,%6,%7}, {%8,%9}, {%0,%1,%2,%3};"
        : "+f"(d[0]), "+f"(d[1]), "+f"(d[2]), "+f"(d[3])
        : "r"(a[0]), "r"(a[1]), "r"(a[2]), "r"(a[3]), "r"(b0), "r"(b1));
}
__device__ __forceinline__ uint32_t packsplit(float x, float y, uint32_t& lo) {
    uint32_t hp;
    asm("cvt.rn.bf16x2.f32 %0, %1, %2;" : "=r"(hp) : "f"(y), "f"(x));
    float hx = __uint_as_float(hp << 16);
    float hy = __uint_as_float(hp & 0xffff0000u);
    float lx = x - hx, ly = y - hy;
    asm("cvt.rn.bf16x2.f32 %0, %1, %2;" : "=r"(lo) : "f"(ly), "f"(lx));
    return hp;
}
// fast 2^t on FMA pipe (t <= 0 in all uses); |rel err| ~ 2.4e-6
__device__ __forceinline__ float e2(float t) {
    t = fmaxf(t, -124.0f);
    int i = __float2int_rn(t);
    float f = t - (float)i;
    float p = 1.3333558146e-3f;
    p = fmaf(p, f, 9.6181291076e-3f);
    p = fmaf(p, f, 5.5504108664e-2f);
    p = fmaf(p, f, 2.4022650696e-1f);
    p = fmaf(p, f, 6.9314718056e-1f);
    p = fmaf(p, f, 1.0f);
    return __int_as_float((i << 23) + __float_as_int(p));
}
#define EXPSCALE 11.541560327111707f   // 8 * log2(e)

// ---------------- fp32 -> bf16 hi/lo split ----------------
template<int SEL>
__global__ __launch_bounds__(256) void split_kernel(const float* __restrict__ srcp, int n4) {
    const float* src = (SEL == 3) ? (const float*)g_attn : srcp;
    __nv_bfloat16* hi = (SEL==0) ? g_xhi : (SEL==1) ? g_wqh : (SEL==2) ? g_woh : g_ahi;
    __nv_bfloat16* lo = (SEL==0) ? g_xlo : (SEL==1) ? g_wql : (SEL==2) ? g_wol : g_alo;
    int i = blockIdx.x * 256 + threadIdx.x;
    if (i >= n4) return;
    float4 v = ((const float4*)src)[i];
    __nv_bfloat16 h0 = __float2bfloat16(v.x);
    __nv_bfloat16 h1 = __float2bfloat16(v.y);
    __nv_bfloat16 h2 = __float2bfloat16(v.z);
    __nv_bfloat16 h3 = __float2bfloat16(v.w);
    __nv_bfloat16 l0 = __float2bfloat16(v.x - __bfloat162float(h0));
    __nv_bfloat16 l1 = __float2bfloat16(v.y - __bfloat162float(h1));
    __nv_bfloat16 l2 = __float2bfloat16(v.z - __bfloat162float(h2));
    __nv_bfloat16 l3 = __float2bfloat16(v.w - __bfloat162float(h3));
    ushort4 hv, lv;
    hv.x = *(unsigned short*)&h0; hv.y = *(unsigned short*)&h1;
    hv.z = *(unsigned short*)&h2; hv.w = *(unsigned short*)&h3;
    lv.x = *(unsigned short*)&l0; lv.y = *(unsigned short*)&l1;
    lv.z = *(unsigned short*)&l2; lv.w = *(unsigned short*)&l3;
    ((ushort4*)hi)[i] = hv;
    ((ushort4*)lo)[i] = lv;
}

// ---------------- HMMA GEMM (bf16 split, 3-term) ----------------
// 512 threads, 16 warps, warp tile 32x32. Synchronous loads (R4-proven),
// single smem buffer, two syncs per chunk. 16 warps/SM hide ldsm/MMA latency.
#define LDP 72
#define CH_ELEMS  (128*LDP)
#define GEMM_SMEM (4*CH_ELEMS*2)               // Ahi, Alo, Bhi, Blo (bytes)

template<int EPI>
__global__ __launch_bounds__(512) void hmma_gemm(float* __restrict__ Cout) {
    const __nv_bfloat16* base[4] = {
        EPI ? g_ahi : g_xhi, EPI ? g_alo : g_xlo,
        EPI ? g_woh : g_wqh, EPI ? g_wol : g_wql };

    extern __shared__ __nv_bfloat16 sm[];

    int tid = threadIdx.x, lane = tid & 31, wid = tid >> 5;
    int m0 = blockIdx.y * 128, n0 = blockIdx.x * 128;
    int wm = (wid & 3) * 32;          // 4 warp-rows
    int wn = (wid >> 2) * 32;         // 4 warp-cols

    float acc[2][4][4];
#pragma unroll
    for (int i = 0; i < 2; i++)
#pragma unroll
        for (int j = 0; j < 4; j++)
#pragma unroll
            for (int q = 0; q < 4; q++) acc[i][j][q] = 0.0f;

    uint32_t smb = smem_u32(sm);

    for (int ck = 0; ck < 16; ck++) {
        int k0 = ck * 64;
        __syncthreads();
        // 4 tiles x 1024 16B-slots, 512 threads -> 2 slots per tile per thread
#pragma unroll
        for (int t = 0; t < 4; t++) {
            const __nv_bfloat16* src = base[t];
            int rbase = (t < 2) ? m0 : n0;
#pragma unroll
            for (int p = 0; p < 2; p++) {
                int slot = p * 512 + tid;            // 0..1023
                int r = slot >> 3, c = (slot & 7) * 8;
                *(uint4*)&sm[t*CH_ELEMS + r*LDP + c] =
                    *(const uint4*)&src[(size_t)(rbase + r) * EMB + k0 + c];
            }
        }
        __syncthreads();

        uint32_t asb0 = smb + (uint32_t)(0*CH_ELEMS) * 2;
        uint32_t asb1 = smb + (uint32_t)(1*CH_ELEMS) * 2;
        uint32_t bsb0 = smb + (uint32_t)(2*CH_ELEMS) * 2;
        uint32_t bsb1 = smb + (uint32_t)(3*CH_ELEMS) * 2;

#pragma unroll
        for (int kc = 0; kc < 64; kc += 16) {
            uint32_t ah[2][4], al[2][4];
#pragma unroll
            for (int mi = 0; mi < 2; mi++) {
                uint32_t off = (uint32_t)((wm + mi*16 + (lane & 15)) * LDP
                                           + kc + (lane >> 4) * 8) * 2;
                ldsm_x4(ah[mi], asb0 + off);
                ldsm_x4(al[mi], asb1 + off);
            }
#pragma unroll
            for (int nj = 0; nj < 2; nj++) {
                uint32_t boff = (uint32_t)((wn + nj*16 + (lane & 7) + ((lane >> 4) & 1) * 8) * LDP
                                           + kc + ((lane >> 3) & 1) * 8) * 2;
                uint32_t bh[4], bl[4];
                ldsm_x4(bh, bsb0 + boff);
                ldsm_x4(bl, bsb1 + boff);
#pragma unroll
                for (int s2 = 0; s2 < 2; s2++) {
#pragma unroll
                    for (int mi = 0; mi < 2; mi++) {
                        float* d = acc[mi][nj*2 + s2];
                        mma16816(d, ah[mi], bh[s2*2], bh[s2*2+1]);
                        mma16816(d, ah[mi], bl[s2*2], bl[s2*2+1]);
                        mma16816(d, al[mi], bh[s2*2], bh[s2*2+1]);
                    }
                }
            }
        }
    }

#pragma unroll
    for (int mi = 0; mi < 2; mi++) {
#pragma unroll
        for (int ni = 0; ni < 4; ni++) {
            float* d = acc[mi][ni];
            int mrow0 = m0 + wm + mi*16 + (lane >> 2);
            int ncol0 = n0 + wn + ni*8 + 2*(lane & 3);
            if (EPI == 0) {
#pragma unroll
                for (int h2 = 0; h2 < 2; h2++) {
                    int m = mrow0 + h2*8;
                    int bb = m >> 11, t = m & 2047;
#pragma unroll
                    for (int c2 = 0; c2 < 2; c2++) {
                        int n  = ncol0 + c2;
                        int di = n / 48;
                        int ki = (n >> 4) % 3;
                        int hh = n & 15;
                        float v = d[h2*2 + c2];
                        __nv_bfloat16 hb = __float2bfloat16(v);
                        __nv_bfloat16 lb = __float2bfloat16(v - __bfloat162float(hb));
                        if (ki == 2) {
                            size_t dst = ((size_t)(bb*HEADS + hh) * HDIM + di) * SEQ + t;
                            g_vth[dst] = hb; g_vtl[dst] = lb;
                        } else {
                            size_t dst = ((size_t)(bb*HEADS + hh) * SEQ + t) * HDIM + di;
                            if (ki == 0) { g_qh[dst] = hb; g_ql[dst] = lb; }
                            else         { g_kh[dst] = hb; g_kl[dst] = lb; }
                        }
                    }
                }
            } else {
                float2 r0; r0.x = d[0]; r0.y = d[1];
                float2 r1; r1.x = d[2]; r1.y = d[3];
                *(float2*)&Cout[(size_t)mrow0       * EMB + ncol0] = r0;
                *(float2*)&Cout[(size_t)(mrow0 + 8) * EMB + ncol0] = r1;
            }
        }
    }
}

// ---------------- HMMA flash attention ----------------
// 256 threads, 8 warps, warp tile 16 q-rows x 64 keys. Same math as R4.
#define ALDP 72
#define ATT_SMEM ((2*128 + 4*64) * ALDP * 2)

__global__ __launch_bounds__(256) void attn_hmma() {
    extern __shared__ __nv_bfloat16 sm[];
    __nv_bfloat16 *Qh = sm,              *Ql = Qh + 128*ALDP;
    __nv_bfloat16 *Kh = Ql + 128*ALDP,   *Kl = Kh + 64*ALDP;
    __nv_bfloat16 *Vh = Kl + 64*ALDP,    *Vl = Vh + 64*ALDP;

    int tid = threadIdx.x, lane = tid & 31, wid = tid >> 5;
    int bh = blockIdx.y, q0 = blockIdx.x * 128;
    int wm = wid * 16;                          // 8 warps x 16 rows

    size_t qgbase = ((size_t)bh * SEQ + q0) * HDIM;
#pragma unroll
    for (int p = 0; p < 4; p++) {
        int slot = p * 256 + tid;               // 0..1023
        int r = slot >> 3, c = (slot & 7) * 8;
        *(uint4*)&Qh[r*ALDP + c] = *(const uint4*)&g_qh[qgbase + (size_t)r*HDIM + c];
        *(uint4*)&Ql[r*ALDP + c] = *(const uint4*)&g_ql[qgbase + (size_t)r*HDIM + c];
    }

    float O[8][4];
#pragma unroll
    for (int j = 0; j < 8; j++)
#pragma unroll
        for (int q = 0; q < 4; q++) O[j][q] = 0.0f;
    float lacc[2] = {0.f, 0.f};
    float mrun[2] = {-1e30f, -1e30f};

    uint32_t qsbh = smem_u32(Qh), qsbl = smem_u32(Ql);
    uint32_t ksbh = smem_u32(Kh), ksbl = smem_u32(Kl);
    uint32_t vsbh = smem_u32(Vh), vsbl = smem_u32(Vl);

    const size_t kgbase = (size_t)bh * SEQ * HDIM;
    const size_t vgbase = (size_t)bh * HDIM * SEQ;

    for (int kt = 0; kt < SEQ/64; kt++) {
        __syncthreads();
#pragma unroll
        for (int p = 0; p < 2; p++) {
            int slot = p * 256 + tid;           // 0..511 over 64x64 tile
            int r = slot >> 3, c = (slot & 7) * 8;
            *(uint4*)&Kh[r*ALDP + c] = *(const uint4*)&g_kh[kgbase + (size_t)(kt*64 + r)*HDIM + c];
            *(uint4*)&Kl[r*ALDP + c] = *(const uint4*)&g_kl[kgbase + (size_t)(kt*64 + r)*HDIM + c];
            *(uint4*)&Vh[r*ALDP + c] = *(const uint4*)&g_vth[vgbase + (size_t)r*SEQ + kt*64 + c];
            *(uint4*)&Vl[r*ALDP + c] = *(const uint4*)&g_vtl[vgbase + (size_t)r*SEQ + kt*64 + c];
        }
        __syncthreads();

        // ---- S = Q K^T  (16 x 64 per warp) ----
        float S[8][4];
#pragma unroll
        for (int j = 0; j < 8; j++)
#pragma unroll
            for (int q = 0; q < 4; q++) S[j][q] = 0.0f;

#pragma unroll
        for (int ks = 0; ks < 4; ks++) {
            uint32_t qh[4], ql[4];
            uint32_t off = (uint32_t)((wm + (lane & 15)) * ALDP
                                       + ks*16 + (lane >> 4) * 8) * 2;
            ldsm_x4(qh, qsbh + off);
            ldsm_x4(ql, qsbl + off);
#pragma unroll
            for (int nj = 0; nj < 4; nj++) {
                uint32_t boff = (uint32_t)((nj*16 + (lane & 7) + ((lane >> 4) & 1) * 8) * ALDP
                                           + ks*16 + ((lane >> 3) & 1) * 8) * 2;
                uint32_t kh[4], kl[4];
                ldsm_x4(kh, ksbh + boff);
                ldsm_x4(kl, ksbl + boff);
#pragma unroll
                for (int s2 = 0; s2 < 2; s2++) {
                    float* d = S[nj*2 + s2];
                    mma16816(d, qh, kh[s2*2], kh[s2*2+1]);
                    mma16816(d, qh, kl[s2*2], kl[s2*2+1]);
                    mma16816(d, ql, kh[s2*2], kh[s2*2+1]);
                }
            }
        }

        // ---- online softmax (rows lane>>2 and +8) ----
        float tmx[2] = {-1e30f, -1e30f};
#pragma unroll
        for (int ni = 0; ni < 8; ni++) {
            tmx[0] = fmaxf(tmx[0], fmaxf(S[ni][0], S[ni][1]));
            tmx[1] = fmaxf(tmx[1], fmaxf(S[ni][2], S[ni][3]));
        }
#pragma unroll
        for (int i = 0; i < 2; i++) {
            tmx[i] = fmaxf(tmx[i], __shfl_xor_sync(0xffffffffu, tmx[i], 1));
            tmx[i] = fmaxf(tmx[i], __shfl_xor_sync(0xffffffffu, tmx[i], 2));
        }
        float corr[2];
#pragma unroll
        for (int i = 0; i < 2; i++) {
            float mn = fmaxf(mrun[i], tmx[i]);
            corr[i] = e2((mrun[i] - mn) * EXPSCALE);
            mrun[i] = mn;
            lacc[i] *= corr[i];
        }
#pragma unroll
        for (int ni = 0; ni < 8; ni++) {
            O[ni][0] *= corr[0];
            O[ni][1] *= corr[0];
            O[ni][2] *= corr[1];
            O[ni][3] *= corr[1];
        }
#pragma unroll
        for (int ni = 0; ni < 8; ni++) {
            float p0 = e2((S[ni][0] - mrun[0]) * EXPSCALE);
            float p1 = e2((S[ni][1] - mrun[0]) * EXPSCALE);
            float p2 = e2((S[ni][2] - mrun[1]) * EXPSCALE);
            float p3 = e2((S[ni][3] - mrun[1]) * EXPSCALE);
            S[ni][0] = p0; S[ni][1] = p1;
            S[ni][2] = p2; S[ni][3] = p3;
            lacc[0] += p0 + p1;
            lacc[1] += p2 + p3;
        }

        // ---- O += P @ V ----
#pragma unroll
        for (int ks = 0; ks < 4; ks++) {
            uint32_t pah[4], pal[4];
            pah[0] = packsplit(S[2*ks  ][0], S[2*ks  ][1], pal[0]);
            pah[1] = packsplit(S[2*ks  ][2], S[2*ks  ][3], pal[1]);
            pah[2] = packsplit(S[2*ks+1][0], S[2*ks+1][1], pal[2]);
            pah[3] = packsplit(S[2*ks+1][2], S[2*ks+1][3], pal[3]);
#pragma unroll
            for (int dj = 0; dj < 4; dj++) {
                uint32_t boff = (uint32_t)((dj*16 + (lane & 7) + ((lane >> 4) & 1) * 8) * ALDP
                                           + ks*16 + ((lane >> 3) & 1) * 8) * 2;
                uint32_t vh[4], vl[4];
                ldsm_x4(vh, vsbh + boff);
                ldsm_x4(vl, vsbl + boff);
#pragma unroll
                for (int s2 = 0; s2 < 2; s2++) {
                    float* d = O[dj*2 + s2];
                    mma16816(d, pah, vh[s2*2], vh[s2*2+1]);
                    mma16816(d, pah, vl[s2*2], vl[s2*2+1]);
                    mma16816(d, pal, vh[s2*2], vh[s2*2+1]);
                }
            }
        }
    }

    // ---- finalize ----
    float inv[2];
#pragma unroll
    for (int i = 0; i < 2; i++) {
        lacc[i] += __shfl_xor_sync(0xffffffffu, lacc[i], 1);
        lacc[i] += __shfl_xor_sync(0xffffffffu, lacc[i], 2);
        inv[i] = 1.0f / lacc[i];
    }
    int b = bh >> 4, h = bh & 15;
#pragma unroll
    for (int h2 = 0; h2 < 2; h2++) {
        int m = q0 + wm + (lane >> 2) + h2*8;
        float* dst = g_attn + ((size_t)b * SEQ + m) * EMB + h * HDIM;
        float iv = inv[h2];
#pragma unroll
        for (int ni = 0; ni < 8; ni++) {
            float2 r;
            r.x = O[ni][h2*2+0] * iv;
            r.y = O[ni][h2*2+1] * iv;
            *(float2*)&dst[ni*8 + 2*(lane & 3)] = r;
        }
    }
}

// ---------------------------------------------------------------------------
extern "C" void kernel_launch(void* const* d_in, const int* in_sizes, int n_in,
                              void* d_out, int out_size) {
    const float* x     = (const float*)d_in[0];   // [B,T,E]
    const float* w_qkv = (const float*)d_in[1];   // [3E,E]
    const float* w_out = (const float*)d_in[2];   // [E,E]
    float* out = (float*)d_out;                   // [B,T,E]

    cudaFuncSetAttribute(hmma_gemm<0>, cudaFuncAttributeMaxDynamicSharedMemorySize, GEMM_SMEM);
    cudaFuncSetAttribute(hmma_gemm<1>, cudaFuncAttributeMaxDynamicSharedMemorySize, GEMM_SMEM);
    cudaFuncSetAttribute(attn_hmma,    cudaFuncAttributeMaxDynamicSharedMemorySize, ATT_SMEM);

    // 1) split inputs to bf16 hi/lo
    split_kernel<0><<<(MROWS*EMB/4 + 255)/256, 256>>>(x,     MROWS*EMB/4);
    split_kernel<1><<<(NQKV*EMB/4  + 255)/256, 256>>>(w_qkv, NQKV*EMB/4);
    split_kernel<2><<<(EMB*EMB/4   + 255)/256, 256>>>(w_out, EMB*EMB/4);

    // 2) QKV projection (HMMA, 512 threads / 16 warps)
    hmma_gemm<0><<<dim3(NQKV/128, MROWS/128), 512, GEMM_SMEM>>>(nullptr);

    // 3) HMMA flash attention (256 threads / 8 warps)
    attn_hmma<<<dim3(SEQ/128, BATCH*HEADS), 256, ATT_SMEM>>>();

    // 4) split attention output, then output projection
    split_kernel<3><<<(MROWS*EMB/4 + 255)/256, 256>>>(nullptr, MROWS*EMB/4);
    hmma_gemm<1><<<dim3(EMB/128, MROWS/128), 512, GEMM_SMEM>>>(out);
}

// round 11
// speedup vs baseline: 1.5943x; 1.1646x over previous
#include <cuda_runtime.h>
#include <cuda_bf16.h>
#include <cstdint>

#define BATCH 2
#define SEQ   2048
#define EMB   1024
#define HEADS 16
#define HDIM  64
#define MROWS (BATCH*SEQ)   // 4096
#define NQKV  (3*EMB)       // 3072
#define QKVN  (BATCH*HEADS*SEQ*HDIM)

// ---------------- scratch (device globals; no runtime alloc) ----------------
__device__ float g_attn[MROWS*EMB];              // [b,t,(h d)] fp32

__device__ __nv_bfloat16 g_xhi[MROWS*EMB],  g_xlo[MROWS*EMB];
__device__ __nv_bfloat16 g_wqh[NQKV*EMB],   g_wql[NQKV*EMB];
__device__ __nv_bfloat16 g_woh[EMB*EMB],    g_wol[EMB*EMB];
__device__ __nv_bfloat16 g_ahi[MROWS*EMB],  g_alo[MROWS*EMB];

__device__ __nv_bfloat16 g_qh[QKVN], g_ql[QKVN];   // [b,h,t,d]
__device__ __nv_bfloat16 g_kh[QKVN], g_kl[QKVN];   // [b,h,t,d]
__device__ __nv_bfloat16 g_vth[QKVN], g_vtl[QKVN]; // [b,h,d,t]  (transposed)

// ---------------- helpers ----------------
__device__ __forceinline__ uint32_t smem_u32(const void* p) {
    uint32_t a;
    asm("{ .reg .u64 t; cvta.to.shared.u64 t, %1; cvt.u32.u64 %0, t; }" : "=r"(a) : "l"(p));
    return a;
}
__device__ __forceinline__ void cp16(uint32_t s, const void* g) {
    asm volatile("cp.async.cg.shared.global [%0], [%1], 16;" :: "r"(s), "l"(g));
}
#define CP_COMMIT() asm volatile("cp.async.commit_group;" ::: "memory")
#define CP_WAIT0()  asm volatile("cp.async.wait_group 0;" ::: "memory")

__device__ __forceinline__ void ldsm_x4(uint32_t* r, uint32_t addr) {
    asm volatile("ldmatrix.sync.aligned.m8n8.x4.shared.b16 {%0,%1,%2,%3}, [%4];"
        : "=r"(r[0]), "=r"(r[1]), "=r"(r[2]), "=r"(r[3]) : "r"(addr));
}
__device__ __forceinline__ void mma16816(float* d, const uint32_t* a, uint32_t b0, uint32_t b1) {
    asm volatile("mma.sync.aligned.m16n8k16.row.col.f32.bf16.bf16.f32 "
        "{%0,%1,%2,%3}, {%4,%5,%6,%7}, {%8,%9}, {%0,%1,%2,%3};"
        : "+f"(d[0]), "+f"(d[1]), "+f"(d[2]), "+f"(d[3])
        : "r"(a[0]), "r"(a[1]), "r"(a[2]), "r"(a[3]), "r"(b0), "r"(b1));
}
__device__ __forceinline__ uint32_t packsplit(float x, float y, uint32_t& lo) {
    uint32_t hp;
    asm("cvt.rn.bf16x2.f32 %0, %1, %2;" : "=r"(hp) : "f"(y), "f"(x));
    float hx = __uint_as_float(hp << 16);
    float hy = __uint_as_float(hp & 0xffff0000u);
    float lx = x - hx, ly = y - hy;
    asm("cvt.rn.bf16x2.f32 %0, %1, %2;" : "=r"(lo) : "f"(ly), "f"(lx));
    return hp;
}
// fast 2^t on FMA pipe (t <= 0 in all uses); |rel err| ~ 2.4e-6
__device__ __forceinline__ float e2(float t) {
    t = fmaxf(t, -124.0f);
    int i = __float2int_rn(t);
    float f = t - (float)i;
    float p = 1.3333558146e-3f;
    p = fmaf(p, f, 9.6181291076e-3f);
    p = fmaf(p, f, 5.5504108664e-2f);
    p = fmaf(p, f, 2.4022650696e-1f);
    p = fmaf(p, f, 6.9314718056e-1f);
    p = fmaf(p, f, 1.0f);
    return __int_as_float((i << 23) + __float_as_int(p));
}
#define EXPSCALE 11.541560327111707f   // 8 * log2(e)

// ---------------- fp32 -> bf16 hi/lo split ----------------
template<int SEL>
__global__ __launch_bounds__(256) void split_kernel(const float* __restrict__ srcp, int n4) {
    const float* src = (SEL == 3) ? (const float*)g_attn : srcp;
    __nv_bfloat16* hi = (SEL==0) ? g_xhi : (SEL==1) ? g_wqh : (SEL==2) ? g_woh : g_ahi;
    __nv_bfloat16* lo = (SEL==0) ? g_xlo : (SEL==1) ? g_wql : (SEL==2) ? g_wol : g_alo;
    int i = blockIdx.x * 256 + threadIdx.x;
    if (i >= n4) return;
    float4 v = ((const float4*)src)[i];
    __nv_bfloat16 h0 = __float2bfloat16(v.x);
    __nv_bfloat16 h1 = __float2bfloat16(v.y);
    __nv_bfloat16 h2 = __float2bfloat16(v.z);
    __nv_bfloat16 h3 = __float2bfloat16(v.w);
    __nv_bfloat16 l0 = __float2bfloat16(v.x - __bfloat162float(h0));
    __nv_bfloat16 l1 = __float2bfloat16(v.y - __bfloat162float(h1));
    __nv_bfloat16 l2 = __float2bfloat16(v.z - __bfloat162float(h2));
    __nv_bfloat16 l3 = __float2bfloat16(v.w - __bfloat162float(h3));
    ushort4 hv, lv;
    hv.x = *(unsigned short*)&h0; hv.y = *(unsigned short*)&h1;
    hv.z = *(unsigned short*)&h2; hv.w = *(unsigned short*)&h3;
    lv.x = *(unsigned short*)&l0; lv.y = *(unsigned short*)&l1;
    lv.z = *(unsigned short*)&l2; lv.w = *(unsigned short*)&l3;
    ((ushort4*)hi)[i] = hv;
    ((ushort4*)lo)[i] = lv;
}

// ---------------- HMMA GEMM (bf16 split, 3-term) ----------------
// 512 threads / 16 warps, warp tile 32x32. Register double-buffer:
// LDG(ck+1)->regs overlaps compute(ck); STS to alternating smem buffer;
// ONE __syncthreads per chunk. Index mapping identical to the R9-verified
// synchronous sweep (slot = p*512+tid over the full 128x64 tile).
#define LDP 72
#define CH_ELEMS  (128*LDP)
#define BUF_ELEMS (4*CH_ELEMS)
#define GEMM_SMEM (2*BUF_ELEMS*2)              // two buffers, bytes

template<int EPI>
__global__ __launch_bounds__(512) void hmma_gemm(float* __restrict__ Cout) {
    const __nv_bfloat16* base[4] = {
        EPI ? g_ahi : g_xhi, EPI ? g_alo : g_xlo,
        EPI ? g_woh : g_wqh, EPI ? g_wol : g_wql };

    extern __shared__ __nv_bfloat16 sm[];

    int tid = threadIdx.x, lane = tid & 31, wid = tid >> 5;
    int m0 = blockIdx.y * 128, n0 = blockIdx.x * 128;
    int wm = (wid & 3) * 32;
    int wn = (wid >> 2) * 32;

    float acc[2][4][4];
#pragma unroll
    for (int i = 0; i < 2; i++)
#pragma unroll
        for (int j = 0; j < 4; j++)
#pragma unroll
            for (int q = 0; q < 4; q++) acc[i][j][q] = 0.0f;

    uint32_t smb = smem_u32(sm);

    uint4 pf[4][2];
    auto ldg_chunk = [&](int k0) {
#pragma unroll
        for (int t = 0; t < 4; t++) {
            const __nv_bfloat16* src = base[t];
            int rbase = (t < 2) ? m0 : n0;
#pragma unroll
            for (int p = 0; p < 2; p++) {
                int slot = p * 512 + tid;            // 0..1023, full tile sweep
                int r = slot >> 3, c = (slot & 7) * 8;
                pf[t][p] = *(const uint4*)&src[(size_t)(rbase + r) * EMB + k0 + c];
            }
        }
    };

    ldg_chunk(0);

    for (int ck = 0; ck < 16; ck++) {
        int buf = ck & 1;
#pragma unroll
        for (int t = 0; t < 4; t++) {
#pragma unroll
            for (int p = 0; p < 2; p++) {
                int slot = p * 512 + tid;
                int r = slot >> 3, c = (slot & 7) * 8;
                *(uint4*)&sm[buf*BUF_ELEMS + t*CH_ELEMS + r*LDP + c] = pf[t][p];
            }
        }
        __syncthreads();
        if (ck < 15) ldg_chunk((ck + 1) * 64);     // overlaps with compute below

        uint32_t asb0 = smb + (uint32_t)(buf*BUF_ELEMS + 0*CH_ELEMS) * 2;
        uint32_t asb1 = smb + (uint32_t)(buf*BUF_ELEMS + 1*CH_ELEMS) * 2;
        uint32_t bsb0 = smb + (uint32_t)(buf*BUF_ELEMS + 2*CH_ELEMS) * 2;
        uint32_t bsb1 = smb + (uint32_t)(buf*BUF_ELEMS + 3*CH_ELEMS) * 2;

#pragma unroll
        for (int kc = 0; kc < 64; kc += 16) {
            uint32_t ah[2][4], al[2][4];
#pragma unroll
            for (int mi = 0; mi < 2; mi++) {
                uint32_t off = (uint32_t)((wm + mi*16 + (lane & 15)) * LDP
                                           + kc + (lane >> 4) * 8) * 2;
                ldsm_x4(ah[mi], asb0 + off);
                ldsm_x4(al[mi], asb1 + off);
            }
#pragma unroll
            for (int nj = 0; nj < 2; nj++) {
                uint32_t boff = (uint32_t)((wn + nj*16 + (lane & 7) + ((lane >> 4) & 1) * 8) * LDP
                                           + kc + ((lane >> 3) & 1) * 8) * 2;
                uint32_t bh[4], bl[4];
                ldsm_x4(bh, bsb0 + boff);
                ldsm_x4(bl, bsb1 + boff);
#pragma unroll
                for (int s2 = 0; s2 < 2; s2++) {
#pragma unroll
                    for (int mi = 0; mi < 2; mi++) {
                        float* d = acc[mi][nj*2 + s2];
                        mma16816(d, ah[mi], bh[s2*2], bh[s2*2+1]);
                        mma16816(d, ah[mi], bl[s2*2], bl[s2*2+1]);
                        mma16816(d, al[mi], bh[s2*2], bh[s2*2+1]);
                    }
                }
            }
        }
    }

#pragma unroll
    for (int mi = 0; mi < 2; mi++) {
#pragma unroll
        for (int ni = 0; ni < 4; ni++) {
            float* d = acc[mi][ni];
            int mrow0 = m0 + wm + mi*16 + (lane >> 2);
            int ncol0 = n0 + wn + ni*8 + 2*(lane & 3);
            if (EPI == 0) {
#pragma unroll
                for (int h2 = 0; h2 < 2; h2++) {
                    int m = mrow0 + h2*8;
                    int bb = m >> 11, t = m & 2047;
#pragma unroll
                    for (int c2 = 0; c2 < 2; c2++) {
                        int n  = ncol0 + c2;
                        int di = n / 48;
                        int ki = (n >> 4) % 3;
                        int hh = n & 15;
                        float v = d[h2*2 + c2];
                        __nv_bfloat16 hb = __float2bfloat16(v);
                        __nv_bfloat16 lb = __float2bfloat16(v - __bfloat162float(hb));
                        if (ki == 2) {
                            size_t dst = ((size_t)(bb*HEADS + hh) * HDIM + di) * SEQ + t;
                            g_vth[dst] = hb; g_vtl[dst] = lb;
                        } else {
                            size_t dst = ((size_t)(bb*HEADS + hh) * SEQ + t) * HDIM + di;
                            if (ki == 0) { g_qh[dst] = hb; g_ql[dst] = lb; }
                            else         { g_kh[dst] = hb; g_kl[dst] = lb; }
                        }
                    }
                }
            } else {
                float2 r0; r0.x = d[0]; r0.y = d[1];
                float2 r1; r1.x = d[2]; r1.y = d[3];
                *(float2*)&Cout[(size_t)mrow0       * EMB + ncol0] = r0;
                *(float2*)&Cout[(size_t)(mrow0 + 8) * EMB + ncol0] = r1;
            }
        }
    }
}

// ---------------- HMMA flash attention ----------------
// R4-proven shape: 128 threads, 4 warps, warp tile 32 q-rows x 64 keys.
// KV tiles double-buffered via cp.async (R5's verified load mapping),
// ONE __syncthreads per key tile.
#define ALDP 72
#define KVT_ELEMS   (64*ALDP)
#define KVBUF_ELEMS (4*KVT_ELEMS)              // Kh, Kl, Vh, Vl
#define ATT_SMEM ((2*128*ALDP + 2*KVBUF_ELEMS) * 2)

__global__ __launch_bounds__(128) void attn_hmma() {
    extern __shared__ __nv_bfloat16 sm[];
    __nv_bfloat16 *Qh = sm, *Ql = Qh + 128*ALDP;
    __nv_bfloat16 *KV  = Ql + 128*ALDP;

    int tid = threadIdx.x, lane = tid & 31, wid = tid >> 5;
    int bh = blockIdx.y, q0 = blockIdx.x * 128;
    int wm = wid * 32;

    uint32_t kvb = smem_u32(KV);

    size_t qgbase = ((size_t)bh * SEQ + q0) * HDIM;
#pragma unroll
    for (int i = 0; i < 8; i++) {
        int slot = i * 128 + tid;
        int r = slot >> 3, c = (slot & 7) * 8;
        *(uint4*)&Qh[r*ALDP + c] = *(const uint4*)&g_qh[qgbase + (size_t)r*HDIM + c];
        *(uint4*)&Ql[r*ALDP + c] = *(const uint4*)&g_ql[qgbase + (size_t)r*HDIM + c];
    }

    const size_t kgbase = (size_t)bh * SEQ * HDIM;
    const size_t vgbase = (size_t)bh * HDIM * SEQ;

    auto load_kv = [&](int kt, int buf) {
        uint32_t dst = kvb + (uint32_t)(buf*KVBUF_ELEMS) * 2;
#pragma unroll
        for (int i = 0; i < 4; i++) {
            int slot = i * 128 + tid;                // 0..511 over 64x64 tile
            int r = slot >> 3, c = (slot & 7) * 8;
            uint32_t so = (uint32_t)(r*ALDP + c) * 2;
            cp16(dst + 0*KVT_ELEMS*2 + so, &g_kh[kgbase + (size_t)(kt*64 + r)*HDIM + c]);
            cp16(dst + 1*KVT_ELEMS*2 + so, &g_kl[kgbase + (size_t)(kt*64 + r)*HDIM + c]);
            cp16(dst + 2*KVT_ELEMS*2 + so, &g_vth[vgbase + (size_t)r*SEQ + kt*64 + c]);
            cp16(dst + 3*KVT_ELEMS*2 + so, &g_vtl[vgbase + (size_t)r*SEQ + kt*64 + c]);
        }
    };

    float O[2][8][4];
#pragma unroll
    for (int i = 0; i < 2; i++)
#pragma unroll
        for (int j = 0; j < 8; j++)
#pragma unroll
            for (int q = 0; q < 4; q++) O[i][j][q] = 0.0f;
    float lacc[4] = {0.f, 0.f, 0.f, 0.f};
    float mrun[4] = {-1e30f, -1e30f, -1e30f, -1e30f};

    uint32_t qsbh = smem_u32(Qh), qsbl = smem_u32(Ql);

    load_kv(0, 0);
    CP_COMMIT();

    for (int kt = 0; kt < SEQ/64; kt++) {
        int buf = kt & 1;
        CP_WAIT0();
        __syncthreads();
        if (kt + 1 < SEQ/64) { load_kv(kt + 1, buf ^ 1); CP_COMMIT(); }

        uint32_t ksbh = kvb + (uint32_t)(buf*KVBUF_ELEMS + 0*KVT_ELEMS) * 2;
        uint32_t ksbl = kvb + (uint32_t)(buf*KVBUF_ELEMS + 1*KVT_ELEMS) * 2;
        uint32_t vsbh = kvb + (uint32_t)(buf*KVBUF_ELEMS + 2*KVT_ELEMS) * 2;
        uint32_t vsbl = kvb + (uint32_t)(buf*KVBUF_ELEMS + 3*KVT_ELEMS) * 2;

        // ---- S = Q K^T ----
        float S[2][8][4];
#pragma unroll
        for (int i = 0; i < 2; i++)
#pragma unroll
            for (int j = 0; j < 8; j++)
#pragma unroll
                for (int q = 0; q < 4; q++) S[i][j][q] = 0.0f;

#pragma unroll
        for (int ks = 0; ks < 4; ks++) {
            uint32_t qh[2][4], ql[2][4];
#pragma unroll
            for (int mi = 0; mi < 2; mi++) {
                uint32_t off = (uint32_t)((wm + mi*16 + (lane & 15)) * ALDP
                                           + ks*16 + (lane >> 4) * 8) * 2;
                ldsm_x4(qh[mi], qsbh + off);
                ldsm_x4(ql[mi], qsbl + off);
            }
#pragma unroll
            for (int nj = 0; nj < 4; nj++) {
                uint32_t boff = (uint32_t)((nj*16 + (lane & 7) + ((lane >> 4) & 1) * 8) * ALDP
                                           + ks*16 + ((lane >> 3) & 1) * 8) * 2;
                uint32_t kh[4], kl[4];
                ldsm_x4(kh, ksbh + boff);
                ldsm_x4(kl, ksbl + boff);
#pragma unroll
                for (int s2 = 0; s2 < 2; s2++) {
#pragma unroll
                    for (int mi = 0; mi < 2; mi++) {
                        float* d = S[mi][nj*2 + s2];
                        mma16816(d, qh[mi], kh[s2*2], kh[s2*2+1]);
                        mma16816(d, qh[mi], kl[s2*2], kl[s2*2+1]);
                        mma16816(d, ql[mi], kh[s2*2], kh[s2*2+1]);
                    }
                }
            }
        }

        // ---- online softmax ----
        float tmx[4] = {-1e30f, -1e30f, -1e30f, -1e30f};
#pragma unroll
        for (int mi = 0; mi < 2; mi++)
#pragma unroll
            for (int ni = 0; ni < 8; ni++) {
                tmx[mi*2+0] = fmaxf(tmx[mi*2+0], fmaxf(S[mi][ni][0], S[mi][ni][1]));
                tmx[mi*2+1] = fmaxf(tmx[mi*2+1], fmaxf(S[mi][ni][2], S[mi][ni][3]));
            }
#pragma unroll
        for (int i = 0; i < 4; i++) {
            tmx[i] = fmaxf(tmx[i], __shfl_xor_sync(0xffffffffu, tmx[i], 1));
            tmx[i] = fmaxf(tmx[i], __shfl_xor_sync(0xffffffffu, tmx[i], 2));
        }
        float corr[4];
#pragma unroll
        for (int i = 0; i < 4; i++) {
            float mn = fmaxf(mrun[i], tmx[i]);
            corr[i] = e2((mrun[i] - mn) * EXPSCALE);
            mrun[i] = mn;
            lacc[i] *= corr[i];
        }
#pragma unroll
        for (int mi = 0; mi < 2; mi++)
#pragma unroll
            for (int ni = 0; ni < 8; ni++) {
                O[mi][ni][0] *= corr[mi*2+0];
                O[mi][ni][1] *= corr[mi*2+0];
                O[mi][ni][2] *= corr[mi*2+1];
                O[mi][ni][3] *= corr[mi*2+1];
            }
#pragma unroll
        for (int mi = 0; mi < 2; mi++)
#pragma unroll
            for (int ni = 0; ni < 8; ni++) {
                float p0 = e2((S[mi][ni][0] - mrun[mi*2+0]) * EXPSCALE);
                float p1 = e2((S[mi][ni][1] - mrun[mi*2+0]) * EXPSCALE);
                float p2 = e2((S[mi][ni][2] - mrun[mi*2+1]) * EXPSCALE);
                float p3 = e2((S[mi][ni][3] - mrun[mi*2+1]) * EXPSCALE);
                S[mi][ni][0] = p0; S[mi][ni][1] = p1;
                S[mi][ni][2] = p2; S[mi][ni][3] = p3;
                lacc[mi*2+0] += p0 + p1;
                lacc[mi*2+1] += p2 + p3;
            }

        // ---- O += P @ V ----
#pragma unroll
        for (int ks = 0; ks < 4; ks++) {
            uint32_t pah[2][4], pal[2][4];
#pragma unroll
            for (int mi = 0; mi < 2; mi++) {
                pah[mi][0] = packsplit(S[mi][2*ks  ][0], S[mi][2*ks  ][1], pal[mi][0]);
                pah[mi][1] = packsplit(S[mi][2*ks  ][2], S[mi][2*ks  ][3], pal[mi][1]);
                pah[mi][2] = packsplit(S[mi][2*ks+1][0], S[mi][2*ks+1][1], pal[mi][2]);
                pah[mi][3] = packsplit(S[mi][2*ks+1][2], S[mi][2*ks+1][3], pal[mi][3]);
            }
#pragma unroll
            for (int dj = 0; dj < 4; dj++) {
                uint32_t boff = (uint32_t)((dj*16 + (lane & 7) + ((lane >> 4) & 1) * 8) * ALDP
                                           + ks*16 + ((lane >> 3) & 1) * 8) * 2;
                uint32_t vh[4], vl[4];
                ldsm_x4(vh, vsbh + boff);
                ldsm_x4(vl, vsbl + boff);
#pragma unroll
                for (int s2 = 0; s2 < 2; s2++) {
#pragma unroll
                    for (int mi = 0; mi < 2; mi++) {
                        float* d = O[mi][dj*2 + s2];
                        mma16816(d, pah[mi], vh[s2*2], vh[s2*2+1]);
                        mma16816(d, pah[mi], vl[s2*2], vl[s2*2+1]);
                        mma16816(d, pal[mi], vh[s2*2], vh[s2*2+1]);
                    }
                }
            }
        }
    }

    // ---- finalize ----
    float inv[4];
#pragma unroll
    for (int i = 0; i < 4; i++) {
        lacc[i] += __shfl_xor_sync(0xffffffffu, lacc[i], 1);
        lacc[i] += __shfl_xor_sync(0xffffffffu, lacc[i], 2);
        inv[i] = 1.0f / lacc[i];
    }
    int b = bh >> 4, h = bh & 15;
#pragma unroll
    for (int mi = 0; mi < 2; mi++) {
#pragma unroll
        for (int h2 = 0; h2 < 2; h2++) {
            int m = q0 + wm + mi*16 + (lane >> 2) + h2*8;
            float* dst = g_attn + ((size_t)b * SEQ + m) * EMB + h * HDIM;
            float iv = inv[mi*2 + h2];
#pragma unroll
            for (int ni = 0; ni < 8; ni++) {
                float2 r;
                r.x = O[mi][ni][h2*2+0] * iv;
                r.y = O[mi][ni][h2*2+1] * iv;
                *(float2*)&dst[ni*8 + 2*(lane & 3)] = r;
            }
        }
    }
}

// ---------------------------------------------------------------------------
extern "C" void kernel_launch(void* const* d_in, const int* in_sizes, int n_in,
                              void* d_out, int out_size) {
    const float* x     = (const float*)d_in[0];   // [B,T,E]
    const float* w_qkv = (const float*)d_in[1];   // [3E,E]
    const float* w_out = (const float*)d_in[2];   // [E,E]
    float* out = (float*)d_out;                   // [B,T,E]

    cudaFuncSetAttribute(hmma_gemm<0>, cudaFuncAttributeMaxDynamicSharedMemorySize, GEMM_SMEM);
    cudaFuncSetAttribute(hmma_gemm<1>, cudaFuncAttributeMaxDynamicSharedMemorySize, GEMM_SMEM);
    cudaFuncSetAttribute(attn_hmma,    cudaFuncAttributeMaxDynamicSharedMemorySize, ATT_SMEM);

    // 1) split inputs to bf16 hi/lo
    split_kernel<0><<<(MROWS*EMB/4 + 255)/256, 256>>>(x,     MROWS*EMB/4);
    split_kernel<1><<<(NQKV*EMB/4  + 255)/256, 256>>>(w_qkv, NQKV*EMB/4);
    split_kernel<2><<<(EMB*EMB/4   + 255)/256, 256>>>(w_out, EMB*EMB/4);

    // 2) QKV projection (HMMA, register double-buffer)
    hmma_gemm<0><<<dim3(NQKV/128, MROWS/128), 512, GEMM_SMEM>>>(nullptr);

    // 3) HMMA flash attention (R4 shape + cp.async KV double-buffer)
    attn_hmma<<<dim3(SEQ/128, BATCH*HEADS), 128, ATT_SMEM>>>();

    // 4) split attention output, then output projection
    split_kernel<3><<<(MROWS*EMB/4 + 255)/256, 256>>>(nullptr, MROWS*EMB/4);
    hmma_gemm<1><<<dim3(EMB/128, MROWS/128), 512, GEMM_SMEM>>>(out);
}

// round 12
// speedup vs baseline: 1.6259x; 1.0198x over previous
#include <cuda_runtime.h>
#include <cuda_bf16.h>
#include <cstdint>

#define BATCH 2
#define SEQ   2048
#define EMB   1024
#define HEADS 16
#define HDIM  64
#define MROWS (BATCH*SEQ)   // 4096
#define NQKV  (3*EMB)       // 3072
#define QKVN  (BATCH*HEADS*SEQ*HDIM)

// ---------------- scratch (device globals; no runtime alloc) ----------------
__device__ float g_attn[MROWS*EMB];              // [b,t,(h d)] fp32

__device__ __nv_bfloat16 g_qh[QKVN], g_ql[QKVN];   // [b,h,t,d]
__device__ __nv_bfloat16 g_kh[QKVN], g_kl[QKVN];   // [b,h,t,d]
__device__ __nv_bfloat16 g_vth[QKVN], g_vtl[QKVN]; // [b,h,d,t]  (transposed)

// ---------------- helpers ----------------
__device__ __forceinline__ uint32_t smem_u32(const void* p) {
    uint32_t a;
    asm("{ .reg .u64 t; cvta.to.shared.u64 t, %1; cvt.u32.u64 %0, t; }" : "=r"(a) : "l"(p));
    return a;
}
__device__ __forceinline__ void cp16(uint32_t s, const void* g) {
    asm volatile("cp.async.cg.shared.global [%0], [%1], 16;" :: "r"(s), "l"(g));
}
#define CP_COMMIT() asm volatile("cp.async.commit_group;" ::: "memory")
#define CP_WAIT0()  asm volatile("cp.async.wait_group 0;" ::: "memory")

__device__ __forceinline__ void ldsm_x4(uint32_t* r, uint32_t addr) {
    asm volatile("ldmatrix.sync.aligned.m8n8.x4.shared.b16 {%0,%1,%2,%3}, [%4];"
        : "=r"(r[0]), "=r"(r[1]), "=r"(r[2]), "=r"(r[3]) : "r"(addr));
}
__device__ __forceinline__ void mma16816(float* d, const uint32_t* a, uint32_t b0, uint32_t b1) {
    asm volatile("mma.sync.aligned.m16n8k16.row.col.f32.bf16.bf16.f32 "
        "{%0,%1,%2,%3}, {%4,%5,%6,%7}, {%8,%9}, {%0,%1,%2,%3};"
        : "+f"(d[0]), "+f"(d[1]), "+f"(d[2]), "+f"(d[3])
        : "r"(a[0]), "r"(a[1]), "r"(a[2]), "r"(a[3]), "r"(b0), "r"(b1));
}
// pack (x low, y high) -> bf16x2 hi word; residual bf16x2 in lo
__device__ __forceinline__ uint32_t packsplit(float x, float y, uint32_t& lo) {
    uint32_t hp;
    asm("cvt.rn.bf16x2.f32 %0, %1, %2;" : "=r"(hp) : "f"(y), "f"(x));
    float hx = __uint_as_float(hp << 16);
    float hy = __uint_as_float(hp & 0xffff0000u);
    float lx = x - hx, ly = y - hy;
    asm("cvt.rn.bf16x2.f32 %0, %1, %2;" : "=r"(lo) : "f"(ly), "f"(lx));
    return hp;
}
// fast 2^t on FMA pipe (t <= 0 in all uses); |rel err| ~ 2.4e-6
__device__ __forceinline__ float e2(float t) {
    t = fmaxf(t, -124.0f);
    int i = __float2int_rn(t);
    float f = t - (float)i;
    float p = 1.3333558146e-3f;
    p = fmaf(p, f, 9.6181291076e-3f);
    p = fmaf(p, f, 5.5504108664e-2f);
    p = fmaf(p, f, 2.4022650696e-1f);
    p = fmaf(p, f, 6.9314718056e-1f);
    p = fmaf(p, f, 1.0f);
    return __int_as_float((i << 23) + __float_as_int(p));
}
#define EXPSCALE 11.541560327111707f   // 8 * log2(e)

// ---------------- HMMA GEMM (fp32 in, bf16 hi/lo split in-register) ----------
// 512 threads / 16 warps, warp tile 32x32. Register double-buffer:
// LDG fp32 (ck+1) overlaps compute(ck); STS converts fp32 -> bf16 hi/lo so
// smem contents are bit-identical to the proven R10 pipeline.
#define LDP 72
#define CH_ELEMS  (128*LDP)
#define BUF_ELEMS (4*CH_ELEMS)                 // Ahi, Alo, Bhi, Blo
#define GEMM_SMEM (2*BUF_ELEMS*2)              // two buffers, bytes

template<int EPI>
__global__ __launch_bounds__(512) void hmma_gemm(const float* __restrict__ Agm,
                                                 const float* __restrict__ Bgm,
                                                 float* __restrict__ Cout) {
    extern __shared__ __nv_bfloat16 sm[];

    int tid = threadIdx.x, lane = tid & 31, wid = tid >> 5;
    int m0 = blockIdx.y * 128, n0 = blockIdx.x * 128;
    int wm = (wid & 3) * 32;
    int wn = (wid >> 2) * 32;

    float acc[2][4][4];
#pragma unroll
    for (int i = 0; i < 2; i++)
#pragma unroll
        for (int j = 0; j < 4; j++)
#pragma unroll
            for (int q = 0; q < 4; q++) acc[i][j][q] = 0.0f;

    uint32_t smb = smem_u32(sm);

    // fp32 tile = 128 rows x 64 cols = 2048 16B-slots; 512 thr x 4 slots each.
    // slot -> r = slot>>4, c = (slot&15)*4
    uint4 pf[2][4];                              // [A,B][part]
    auto ldg_chunk = [&](int k0) {
#pragma unroll
        for (int s = 0; s < 2; s++) {
            const float* src = s ? Bgm : Agm;
            int rbase = s ? n0 : m0;
#pragma unroll
            for (int p = 0; p < 4; p++) {
                int slot = p * 512 + tid;
                int r = slot >> 4, c = (slot & 15) * 4;
                pf[s][p] = *(const uint4*)&src[(size_t)(rbase + r) * EMB + k0 + c];
            }
        }
    };

    ldg_chunk(0);

    for (int ck = 0; ck < 16; ck++) {
        int buf = ck & 1;
#pragma unroll
        for (int s = 0; s < 2; s++) {
#pragma unroll
            for (int p = 0; p < 4; p++) {
                int slot = p * 512 + tid;
                int r = slot >> 4, c = (slot & 15) * 4;
                float4 f = *(float4*)&pf[s][p];
                uint32_t l0, l1;
                uint32_t h0 = packsplit(f.x, f.y, l0);
                uint32_t h1 = packsplit(f.z, f.w, l1);
                uint32_t eo = (uint32_t)(r*LDP + c) * 2;        // byte offset in tile
                char* bp = (char*)sm + (size_t)(buf*BUF_ELEMS)*2;
                uint2 hv; hv.x = h0; hv.y = h1;
                uint2 lv; lv.x = l0; lv.y = l1;
                *(uint2*)(bp + (size_t)(2*s    )*CH_ELEMS*2 + eo) = hv;  // hi tile
                *(uint2*)(bp + (size_t)(2*s + 1)*CH_ELEMS*2 + eo) = lv;  // lo tile
            }
        }
        __syncthreads();
        if (ck < 15) ldg_chunk((ck + 1) * 64);     // overlaps compute below

        uint32_t asb0 = smb + (uint32_t)(buf*BUF_ELEMS + 0*CH_ELEMS) * 2;
        uint32_t asb1 = smb + (uint32_t)(buf*BUF_ELEMS + 1*CH_ELEMS) * 2;
        uint32_t bsb0 = smb + (uint32_t)(buf*BUF_ELEMS + 2*CH_ELEMS) * 2;
        uint32_t bsb1 = smb + (uint32_t)(buf*BUF_ELEMS + 3*CH_ELEMS) * 2;

#pragma unroll
        for (int kc = 0; kc < 64; kc += 16) {
            uint32_t ah[2][4], al[2][4];
#pragma unroll
            for (int mi = 0; mi < 2; mi++) {
                uint32_t off = (uint32_t)((wm + mi*16 + (lane & 15)) * LDP
                                           + kc + (lane >> 4) * 8) * 2;
                ldsm_x4(ah[mi], asb0 + off);
                ldsm_x4(al[mi], asb1 + off);
            }
#pragma unroll
            for (int nj = 0; nj < 2; nj++) {
                uint32_t boff = (uint32_t)((wn + nj*16 + (lane & 7) + ((lane >> 4) & 1) * 8) * LDP
                                           + kc + ((lane >> 3) & 1) * 8) * 2;
                uint32_t bh[4], bl[4];
                ldsm_x4(bh, bsb0 + boff);
                ldsm_x4(bl, bsb1 + boff);
#pragma unroll
                for (int s2 = 0; s2 < 2; s2++) {
#pragma unroll
                    for (int mi = 0; mi < 2; mi++) {
                        float* d = acc[mi][nj*2 + s2];
                        mma16816(d, ah[mi], bh[s2*2], bh[s2*2+1]);
                        mma16816(d, ah[mi], bl[s2*2], bl[s2*2+1]);
                        mma16816(d, al[mi], bh[s2*2], bh[s2*2+1]);
                    }
                }
            }
        }
    }

#pragma unroll
    for (int mi = 0; mi < 2; mi++) {
#pragma unroll
        for (int ni = 0; ni < 4; ni++) {
            float* d = acc[mi][ni];
            int mrow0 = m0 + wm + mi*16 + (lane >> 2);
            int ncol0 = n0 + wn + ni*8 + 2*(lane & 3);
            if (EPI == 0) {
#pragma unroll
                for (int h2 = 0; h2 < 2; h2++) {
                    int m = mrow0 + h2*8;
                    int bb = m >> 11, t = m & 2047;
#pragma unroll
                    for (int c2 = 0; c2 < 2; c2++) {
                        int n  = ncol0 + c2;
                        int di = n / 48;
                        int ki = (n >> 4) % 3;
                        int hh = n & 15;
                        float v = d[h2*2 + c2];
                        __nv_bfloat16 hb = __float2bfloat16(v);
                        __nv_bfloat16 lb = __float2bfloat16(v - __bfloat162float(hb));
                        if (ki == 2) {
                            size_t dst = ((size_t)(bb*HEADS + hh) * HDIM + di) * SEQ + t;
                            g_vth[dst] = hb; g_vtl[dst] = lb;
                        } else {
                            size_t dst = ((size_t)(bb*HEADS + hh) * SEQ + t) * HDIM + di;
                            if (ki == 0) { g_qh[dst] = hb; g_ql[dst] = lb; }
                            else         { g_kh[dst] = hb; g_kl[dst] = lb; }
                        }
                    }
                }
            } else {
                float2 r0; r0.x = d[0]; r0.y = d[1];
                float2 r1; r1.x = d[2]; r1.y = d[3];
                *(float2*)&Cout[(size_t)mrow0       * EMB + ncol0] = r0;
                *(float2*)&Cout[(size_t)(mrow0 + 8) * EMB + ncol0] = r1;
            }
        }
    }
}

// ---------------- HMMA flash attention (R10-proven, unchanged) ---------------
#define ALDP 72
#define KVT_ELEMS   (64*ALDP)
#define KVBUF_ELEMS (4*KVT_ELEMS)              // Kh, Kl, Vh, Vl
#define ATT_SMEM ((2*128*ALDP + 2*KVBUF_ELEMS) * 2)

__global__ __launch_bounds__(128) void attn_hmma() {
    extern __shared__ __nv_bfloat16 sm[];
    __nv_bfloat16 *Qh = sm, *Ql = Qh + 128*ALDP;
    __nv_bfloat16 *KV  = Ql + 128*ALDP;

    int tid = threadIdx.x, lane = tid & 31, wid = tid >> 5;
    int bh = blockIdx.y, q0 = blockIdx.x * 128;
    int wm = wid * 32;

    uint32_t kvb = smem_u32(KV);

    size_t qgbase = ((size_t)bh * SEQ + q0) * HDIM;
#pragma unroll
    for (int i = 0; i < 8; i++) {
        int slot = i * 128 + tid;
        int r = slot >> 3, c = (slot & 7) * 8;
        *(uint4*)&Qh[r*ALDP + c] = *(const uint4*)&g_qh[qgbase + (size_t)r*HDIM + c];
        *(uint4*)&Ql[r*ALDP + c] = *(const uint4*)&g_ql[qgbase + (size_t)r*HDIM + c];
    }

    const size_t kgbase = (size_t)bh * SEQ * HDIM;
    const size_t vgbase = (size_t)bh * HDIM * SEQ;

    auto load_kv = [&](int kt, int buf) {
        uint32_t dst = kvb + (uint32_t)(buf*KVBUF_ELEMS) * 2;
#pragma unroll
        for (int i = 0; i < 4; i++) {
            int slot = i * 128 + tid;                // 0..511 over 64x64 tile
            int r = slot >> 3, c = (slot & 7) * 8;
            uint32_t so = (uint32_t)(r*ALDP + c) * 2;
            cp16(dst + 0*KVT_ELEMS*2 + so, &g_kh[kgbase + (size_t)(kt*64 + r)*HDIM + c]);
            cp16(dst + 1*KVT_ELEMS*2 + so, &g_kl[kgbase + (size_t)(kt*64 + r)*HDIM + c]);
            cp16(dst + 2*KVT_ELEMS*2 + so, &g_vth[vgbase + (size_t)r*SEQ + kt*64 + c]);
            cp16(dst + 3*KVT_ELEMS*2 + so, &g_vtl[vgbase + (size_t)r*SEQ + kt*64 + c]);
        }
    };

    float O[2][8][4];
#pragma unroll
    for (int i = 0; i < 2; i++)
#pragma unroll
        for (int j = 0; j < 8; j++)
#pragma unroll
            for (int q = 0; q < 4; q++) O[i][j][q] = 0.0f;
    float lacc[4] = {0.f, 0.f, 0.f, 0.f};
    float mrun[4] = {-1e30f, -1e30f, -1e30f, -1e30f};

    uint32_t qsbh = smem_u32(Qh), qsbl = smem_u32(Ql);

    load_kv(0, 0);
    CP_COMMIT();

    for (int kt = 0; kt < SEQ/64; kt++) {
        int buf = kt & 1;
        CP_WAIT0();
        __syncthreads();
        if (kt + 1 < SEQ/64) { load_kv(kt + 1, buf ^ 1); CP_COMMIT(); }

        uint32_t ksbh = kvb + (uint32_t)(buf*KVBUF_ELEMS + 0*KVT_ELEMS) * 2;
        uint32_t ksbl = kvb + (uint32_t)(buf*KVBUF_ELEMS + 1*KVT_ELEMS) * 2;
        uint32_t vsbh = kvb + (uint32_t)(buf*KVBUF_ELEMS + 2*KVT_ELEMS) * 2;
        uint32_t vsbl = kvb + (uint32_t)(buf*KVBUF_ELEMS + 3*KVT_ELEMS) * 2;

        // ---- S = Q K^T ----
        float S[2][8][4];
#pragma unroll
        for (int i = 0; i < 2; i++)
#pragma unroll
            for (int j = 0; j < 8; j++)
#pragma unroll
                for (int q = 0; q < 4; q++) S[i][j][q] = 0.0f;

#pragma unroll
        for (int ks = 0; ks < 4; ks++) {
            uint32_t qh[2][4], ql[2][4];
#pragma unroll
            for (int mi = 0; mi < 2; mi++) {
                uint32_t off = (uint32_t)((wm + mi*16 + (lane & 15)) * ALDP
                                           + ks*16 + (lane >> 4) * 8) * 2;
                ldsm_x4(qh[mi], qsbh + off);
                ldsm_x4(ql[mi], qsbl + off);
            }
#pragma unroll
            for (int nj = 0; nj < 4; nj++) {
                uint32_t boff = (uint32_t)((nj*16 + (lane & 7) + ((lane >> 4) & 1) * 8) * ALDP
                                           + ks*16 + ((lane >> 3) & 1) * 8) * 2;
                uint32_t kh[4], kl[4];
                ldsm_x4(kh, ksbh + boff);
                ldsm_x4(kl, ksbl + boff);
#pragma unroll
                for (int s2 = 0; s2 < 2; s2++) {
#pragma unroll
                    for (int mi = 0; mi < 2; mi++) {
                        float* d = S[mi][nj*2 + s2];
                        mma16816(d, qh[mi], kh[s2*2], kh[s2*2+1]);
                        mma16816(d, qh[mi], kl[s2*2], kl[s2*2+1]);
                        mma16816(d, ql[mi], kh[s2*2], kh[s2*2+1]);
                    }
                }
            }
        }

        // ---- online softmax ----
        float tmx[4] = {-1e30f, -1e30f, -1e30f, -1e30f};
#pragma unroll
        for (int mi = 0; mi < 2; mi++)
#pragma unroll
            for (int ni = 0; ni < 8; ni++) {
                tmx[mi*2+0] = fmaxf(tmx[mi*2+0], fmaxf(S[mi][ni][0], S[mi][ni][1]));
                tmx[mi*2+1] = fmaxf(tmx[mi*2+1], fmaxf(S[mi][ni][2], S[mi][ni][3]));
            }
#pragma unroll
        for (int i = 0; i < 4; i++) {
            tmx[i] = fmaxf(tmx[i], __shfl_xor_sync(0xffffffffu, tmx[i], 1));
            tmx[i] = fmaxf(tmx[i], __shfl_xor_sync(0xffffffffu, tmx[i], 2));
        }
        float corr[4];
#pragma unroll
        for (int i = 0; i < 4; i++) {
            float mn = fmaxf(mrun[i], tmx[i]);
            corr[i] = e2((mrun[i] - mn) * EXPSCALE);
            mrun[i] = mn;
            lacc[i] *= corr[i];
        }
#pragma unroll
        for (int mi = 0; mi < 2; mi++)
#pragma unroll
            for (int ni = 0; ni < 8; ni++) {
                O[mi][ni][0] *= corr[mi*2+0];
                O[mi][ni][1] *= corr[mi*2+0];
                O[mi][ni][2] *= corr[mi*2+1];
                O[mi][ni][3] *= corr[mi*2+1];
            }
#pragma unroll
        for (int mi = 0; mi < 2; mi++)
#pragma unroll
            for (int ni = 0; ni < 8; ni++) {
                float p0 = e2((S[mi][ni][0] - mrun[mi*2+0]) * EXPSCALE);
                float p1 = e2((S[mi][ni][1] - mrun[mi*2+0]) * EXPSCALE);
                float p2 = e2((S[mi][ni][2] - mrun[mi*2+1]) * EXPSCALE);
                float p3 = e2((S[mi][ni][3] - mrun[mi*2+1]) * EXPSCALE);
                S[mi][ni][0] = p0; S[mi][ni][1] = p1;
                S[mi][ni][2] = p2; S[mi][ni][3] = p3;
                lacc[mi*2+0] += p0 + p1;
                lacc[mi*2+1] += p2 + p3;
            }

        // ---- O += P @ V ----
#pragma unroll
        for (int ks = 0; ks < 4; ks++) {
            uint32_t pah[2][4], pal[2][4];
#pragma unroll
            for (int mi = 0; mi < 2; mi++) {
                pah[mi][0] = packsplit(S[mi][2*ks  ][0], S[mi][2*ks  ][1], pal[mi][0]);
                pah[mi][1] = packsplit(S[mi][2*ks  ][2], S[mi][2*ks  ][3], pal[mi][1]);
                pah[mi][2] = packsplit(S[mi][2*ks+1][0], S[mi][2*ks+1][1], pal[mi][2]);
                pah[mi][3] = packsplit(S[mi][2*ks+1][2], S[mi][2*ks+1][3], pal[mi][3]);
            }
#pragma unroll
            for (int dj = 0; dj < 4; dj++) {
                uint32_t boff = (uint32_t)((dj*16 + (lane & 7) + ((lane >> 4) & 1) * 8) * ALDP
                                           + ks*16 + ((lane >> 3) & 1) * 8) * 2;
                uint32_t vh[4], vl[4];
                ldsm_x4(vh, vsbh + boff);
                ldsm_x4(vl, vsbl + boff);
#pragma unroll
                for (int s2 = 0; s2 < 2; s2++) {
#pragma unroll
                    for (int mi = 0; mi < 2; mi++) {
                        float* d = O[mi][dj*2 + s2];
                        mma16816(d, pah[mi], vh[s2*2], vh[s2*2+1]);
                        mma16816(d, pah[mi], vl[s2*2], vl[s2*2+1]);
                        mma16816(d, pal[mi], vh[s2*2], vh[s2*2+1]);
                    }
                }
            }
        }
    }

    // ---- finalize ----
    float inv[4];
#pragma unroll
    for (int i = 0; i < 4; i++) {
        lacc[i] += __shfl_xor_sync(0xffffffffu, lacc[i], 1);
        lacc[i] += __shfl_xor_sync(0xffffffffu, lacc[i], 2);
        inv[i] = 1.0f / lacc[i];
    }
    int b = bh >> 4, h = bh & 15;
#pragma unroll
    for (int mi = 0; mi < 2; mi++) {
#pragma unroll
        for (int h2 = 0; h2 < 2; h2++) {
            int m = q0 + wm + mi*16 + (lane >> 2) + h2*8;
            float* dst = g_attn + ((size_t)b * SEQ + m) * EMB + h * HDIM;
            float iv = inv[mi*2 + h2];
#pragma unroll
            for (int ni = 0; ni < 8; ni++) {
                float2 r;
                r.x = O[mi][ni][h2*2+0] * iv;
                r.y = O[mi][ni][h2*2+1] * iv;
                *(float2*)&dst[ni*8 + 2*(lane & 3)] = r;
            }
        }
    }
}

// ---------------------------------------------------------------------------
extern "C" void kernel_launch(void* const* d_in, const int* in_sizes, int n_in,
                              void* d_out, int out_size) {
    const float* x     = (const float*)d_in[0];   // [B,T,E]
    const float* w_qkv = (const float*)d_in[1];   // [3E,E]
    const float* w_out = (const float*)d_in[2];   // [E,E]
    float* out = (float*)d_out;                   // [B,T,E]

    float* gattn;
    cudaGetSymbolAddress((void**)&gattn, g_attn);

    cudaFuncSetAttribute(hmma_gemm<0>, cudaFuncAttributeMaxDynamicSharedMemorySize, GEMM_SMEM);
    cudaFuncSetAttribute(hmma_gemm<1>, cudaFuncAttributeMaxDynamicSharedMemorySize, GEMM_SMEM);
    cudaFuncSetAttribute(attn_hmma,    cudaFuncAttributeMaxDynamicSharedMemorySize, ATT_SMEM);

    // 1) QKV projection (fp32 in, in-register bf16 split) -> q/k/v hi-lo buffers
    hmma_gemm<0><<<dim3(NQKV/128, MROWS/128), 512, GEMM_SMEM>>>(x, w_qkv, nullptr);

    // 2) HMMA flash attention -> fp32 g_attn
    attn_hmma<<<dim3(SEQ/128, BATCH*HEADS), 128, ATT_SMEM>>>();

    // 3) output projection (fp32 in, in-register bf16 split)
    hmma_gemm<1><<<dim3(EMB/128, MROWS/128), 512, GEMM_SMEM>>>(gattn, w_out, out);
}

// round 13
// speedup vs baseline: 2.0309x; 1.2491x over previous
#include <cuda_runtime.h>
#include <cuda_bf16.h>
#include <cstdint>

#define BATCH 2
#define SEQ   2048
#define EMB   1024
#define HEADS 16
#define HDIM  64
#define MROWS (BATCH*SEQ)   // 4096
#define NQKV  (3*EMB)       // 3072
#define QKVN  (BATCH*HEADS*SEQ*HDIM)

// ---------------- scratch (device globals; no runtime alloc) ----------------
__device__ float g_attn[MROWS*EMB];              // [b,t,(h d)] fp32

__device__ __nv_bfloat16 g_qh[QKVN], g_ql[QKVN];   // [b,h,t,d]
__device__ __nv_bfloat16 g_kh[QKVN], g_kl[QKVN];   // [b,h,t,d]
__device__ __nv_bfloat16 g_vth[QKVN], g_vtl[QKVN]; // [b,h,d,t]  (transposed)

// ---------------- helpers ----------------
__device__ __forceinline__ uint32_t smem_u32(const void* p) {
    uint32_t a;
    asm("{ .reg .u64 t; cvta.to.shared.u64 t, %1; cvt.u32.u64 %0, t; }" : "=r"(a) : "l"(p));
    return a;
}
__device__ __forceinline__ void cp16(uint32_t s, const void* g) {
    asm volatile("cp.async.cg.shared.global [%0], [%1], 16;" :: "r"(s), "l"(g));
}
#define CP_COMMIT() asm volatile("cp.async.commit_group;" ::: "memory")
#define CP_WAIT0()  asm volatile("cp.async.wait_group 0;" ::: "memory")

__device__ __forceinline__ void ldsm_x4(uint32_t* r, uint32_t addr) {
    asm volatile("ldmatrix.sync.aligned.m8n8.x4.shared.b16 {%0,%1,%2,%3}, [%4];"
        : "=r"(r[0]), "=r"(r[1]), "=r"(r[2]), "=r"(r[3]) : "r"(addr));
}
__device__ __forceinline__ void mma16816(float* d, const uint32_t* a, uint32_t b0, uint32_t b1) {
    asm volatile("mma.sync.aligned.m16n8k16.row.col.f32.bf16.bf16.f32 "
        "{%0,%1,%2,%3}, {%4,%5,%6,%7}, {%8,%9}, {%0,%1,%2,%3};"
        : "+f"(d[0]), "+f"(d[1]), "+f"(d[2]), "+f"(d[3])
        : "r"(a[0]), "r"(a[1]), "r"(a[2]), "r"(a[3]), "r"(b0), "r"(b1));
}
// pack (x low, y high) -> bf16x2 hi word; residual bf16x2 in lo
__device__ __forceinline__ uint32_t packsplit(float x, float y, uint32_t& lo) {
    uint32_t hp;
    asm("cvt.rn.bf16x2.f32 %0, %1, %2;" : "=r"(hp) : "f"(y), "f"(x));
    float hx = __uint_as_float(hp << 16);
    float hy = __uint_as_float(hp & 0xffff0000u);
    float lx = x - hx, ly = y - hy;
    asm("cvt.rn.bf16x2.f32 %0, %1, %2;" : "=r"(lo) : "f"(ly), "f"(lx));
    return hp;
}
// fast 2^t on FMA pipe (t <= 0 in all uses); |rel err| ~ 2.4e-6
__device__ __forceinline__ float e2(float t) {
    t = fmaxf(t, -124.0f);
    int i = __float2int_rn(t);
    float f = t - (float)i;
    float p = 1.3333558146e-3f;
    p = fmaf(p, f, 9.6181291076e-3f);
    p = fmaf(p, f, 5.5504108664e-2f);
    p = fmaf(p, f, 2.4022650696e-1f);
    p = fmaf(p, f, 6.9314718056e-1f);
    p = fmaf(p, f, 1.0f);
    return __int_as_float((i << 23) + __float_as_int(p));
}
#define EXPSCALE 11.541560327111707f   // 8 * log2(e)

// ---------------- HMMA GEMM (fp32 in, bf16 hi/lo split in-register) ----------
// 512 threads / 16 warps, warp tile 32x32. Register double-buffer.
// EPI 0 (QKV): n-columns re-tiled as {n = 48*d + pair_id} — each block covers
//   2 (ki,hi) pairs x all 64 d. Epilogue writes CONSECUTIVE d (coalesced).
// EPI 1 (out-proj): plain consecutive n, row-major C.
#define LDP 72
#define CH_ELEMS  (128*LDP)
#define BUF_ELEMS (4*CH_ELEMS)                 // Ahi, Alo, Bhi, Blo
#define GEMM_SMEM (2*BUF_ELEMS*2)              // two buffers, bytes

template<int EPI>
__global__ __launch_bounds__(512) void hmma_gemm(const float* __restrict__ Agm,
                                                 const float* __restrict__ Bgm,
                                                 float* __restrict__ Cout) {
    extern __shared__ __nv_bfloat16 sm[];

    int tid = threadIdx.x, lane = tid & 31, wid = tid >> 5;
    int m0 = blockIdx.y * 128, n0 = blockIdx.x * 128;
    int wm = (wid & 3) * 32;
    int wn = (wid >> 2) * 32;

    float acc[2][4][4];
#pragma unroll
    for (int i = 0; i < 2; i++)
#pragma unroll
        for (int j = 0; j < 4; j++)
#pragma unroll
            for (int q = 0; q < 4; q++) acc[i][j][q] = 0.0f;

    uint32_t smb = smem_u32(sm);

    // fp32 tile = 128 rows x 64 cols = 2048 16B-slots; 512 thr x 4 slots each.
    uint4 pf[2][4];                              // [A,B][part]
    auto ldg_chunk = [&](int k0) {
#pragma unroll
        for (int s = 0; s < 2; s++) {
            const float* src = s ? Bgm : Agm;
#pragma unroll
            for (int p = 0; p < 4; p++) {
                int slot = p * 512 + tid;
                int r = slot >> 4, c = (slot & 15) * 4;
                int grow;
                if (s == 0) {
                    grow = m0 + r;
                } else if (EPI == 0) {
                    // in-block col r -> pair (r>>6), d (r&63); w_qkv row = 48*d + pair_id
                    int pair_id = blockIdx.x * 2 + (r >> 6);
                    grow = 48 * (r & 63) + pair_id;
                } else {
                    grow = n0 + r;
                }
                pf[s][p] = *(const uint4*)&src[(size_t)grow * EMB + k0 + c];
            }
        }
    };

    ldg_chunk(0);

    for (int ck = 0; ck < 16; ck++) {
        int buf = ck & 1;
#pragma unroll
        for (int s = 0; s < 2; s++) {
#pragma unroll
            for (int p = 0; p < 4; p++) {
                int slot = p * 512 + tid;
                int r = slot >> 4, c = (slot & 15) * 4;
                float4 f = *(float4*)&pf[s][p];
                uint32_t l0, l1;
                uint32_t h0 = packsplit(f.x, f.y, l0);
                uint32_t h1 = packsplit(f.z, f.w, l1);
                uint32_t eo = (uint32_t)(r*LDP + c) * 2;
                char* bp = (char*)sm + (size_t)(buf*BUF_ELEMS)*2;
                uint2 hv; hv.x = h0; hv.y = h1;
                uint2 lv; lv.x = l0; lv.y = l1;
                *(uint2*)(bp + (size_t)(2*s    )*CH_ELEMS*2 + eo) = hv;
                *(uint2*)(bp + (size_t)(2*s + 1)*CH_ELEMS*2 + eo) = lv;
            }
        }
        __syncthreads();
        if (ck < 15) ldg_chunk((ck + 1) * 64);     // overlaps compute below

        uint32_t asb0 = smb + (uint32_t)(buf*BUF_ELEMS + 0*CH_ELEMS) * 2;
        uint32_t asb1 = smb + (uint32_t)(buf*BUF_ELEMS + 1*CH_ELEMS) * 2;
        uint32_t bsb0 = smb + (uint32_t)(buf*BUF_ELEMS + 2*CH_ELEMS) * 2;
        uint32_t bsb1 = smb + (uint32_t)(buf*BUF_ELEMS + 3*CH_ELEMS) * 2;

#pragma unroll
        for (int kc = 0; kc < 64; kc += 16) {
            uint32_t ah[2][4], al[2][4];
#pragma unroll
            for (int mi = 0; mi < 2; mi++) {
                uint32_t off = (uint32_t)((wm + mi*16 + (lane & 15)) * LDP
                                           + kc + (lane >> 4) * 8) * 2;
                ldsm_x4(ah[mi], asb0 + off);
                ldsm_x4(al[mi], asb1 + off);
            }
#pragma unroll
            for (int nj = 0; nj < 2; nj++) {
                uint32_t boff = (uint32_t)((wn + nj*16 + (lane & 7) + ((lane >> 4) & 1) * 8) * LDP
                                           + kc + ((lane >> 3) & 1) * 8) * 2;
                uint32_t bh[4], bl[4];
                ldsm_x4(bh, bsb0 + boff);
                ldsm_x4(bl, bsb1 + boff);
#pragma unroll
                for (int s2 = 0; s2 < 2; s2++) {
#pragma unroll
                    for (int mi = 0; mi < 2; mi++) {
                        float* d = acc[mi][nj*2 + s2];
                        mma16816(d, ah[mi], bh[s2*2], bh[s2*2+1]);
                        mma16816(d, ah[mi], bl[s2*2], bl[s2*2+1]);
                        mma16816(d, al[mi], bh[s2*2], bh[s2*2+1]);
                    }
                }
            }
        }
    }

#pragma unroll
    for (int mi = 0; mi < 2; mi++) {
#pragma unroll
        for (int ni = 0; ni < 4; ni++) {
            float* d = acc[mi][ni];
            int mrow0 = m0 + wm + mi*16 + (lane >> 2);
            int j0 = wn + ni*8 + 2*(lane & 3);          // in-block col (pair,d)
            if (EPI == 0) {
                int pair_id = blockIdx.x * 2 + (j0 >> 6);
                int ki = pair_id >> 4;                   // pair_id / 16
                int hh = pair_id & 15;
                int d0 = j0 & 63;                        // even
#pragma unroll
                for (int h2 = 0; h2 < 2; h2++) {
                    int m = mrow0 + h2*8;
                    int bb = m >> 11, t = m & 2047;
                    float v0 = d[h2*2 + 0];
                    float v1 = d[h2*2 + 1];
                    uint32_t lw;
                    uint32_t hw = packsplit(v0, v1, lw); // packed (d0, d0+1)
                    if (ki == 2) {
                        size_t dst = ((size_t)(bb*HEADS + hh) * HDIM + d0) * SEQ + t;
                        g_vth[dst]       = __ushort_as_bfloat16((unsigned short)(hw & 0xffff));
                        g_vth[dst + SEQ] = __ushort_as_bfloat16((unsigned short)(hw >> 16));
                        g_vtl[dst]       = __ushort_as_bfloat16((unsigned short)(lw & 0xffff));
                        g_vtl[dst + SEQ] = __ushort_as_bfloat16((unsigned short)(lw >> 16));
                    } else {
                        size_t dst = ((size_t)(bb*HEADS + hh) * SEQ + t) * HDIM + d0;
                        if (ki == 0) {
                            *(uint32_t*)&g_qh[dst] = hw;
                            *(uint32_t*)&g_ql[dst] = lw;
                        } else {
                            *(uint32_t*)&g_kh[dst] = hw;
                            *(uint32_t*)&g_kl[dst] = lw;
                        }
                    }
                }
            } else {
                int ncol0 = n0 + j0;
                float2 r0; r0.x = d[0]; r0.y = d[1];
                float2 r1; r1.x = d[2]; r1.y = d[3];
                *(float2*)&Cout[(size_t)mrow0       * EMB + ncol0] = r0;
                *(float2*)&Cout[(size_t)(mrow0 + 8) * EMB + ncol0] = r1;
            }
        }
    }
}

// ---------------- HMMA flash attention (R10-proven, unchanged) ---------------
#define ALDP 72
#define KVT_ELEMS   (64*ALDP)
#define KVBUF_ELEMS (4*KVT_ELEMS)              // Kh, Kl, Vh, Vl
#define ATT_SMEM ((2*128*ALDP + 2*KVBUF_ELEMS) * 2)

__global__ __launch_bounds__(128) void attn_hmma() {
    extern __shared__ __nv_bfloat16 sm[];
    __nv_bfloat16 *Qh = sm, *Ql = Qh + 128*ALDP;
    __nv_bfloat16 *KV  = Ql + 128*ALDP;

    int tid = threadIdx.x, lane = tid & 31, wid = tid >> 5;
    int bh = blockIdx.y, q0 = blockIdx.x * 128;
    int wm = wid * 32;

    uint32_t kvb = smem_u32(KV);

    size_t qgbase = ((size_t)bh * SEQ + q0) * HDIM;
#pragma unroll
    for (int i = 0; i < 8; i++) {
        int slot = i * 128 + tid;
        int r = slot >> 3, c = (slot & 7) * 8;
        *(uint4*)&Qh[r*ALDP + c] = *(const uint4*)&g_qh[qgbase + (size_t)r*HDIM + c];
        *(uint4*)&Ql[r*ALDP + c] = *(const uint4*)&g_ql[qgbase + (size_t)r*HDIM + c];
    }

    const size_t kgbase = (size_t)bh * SEQ * HDIM;
    const size_t vgbase = (size_t)bh * HDIM * SEQ;

    auto load_kv = [&](int kt, int buf) {
        uint32_t dst = kvb + (uint32_t)(buf*KVBUF_ELEMS) * 2;
#pragma unroll
        for (int i = 0; i < 4; i++) {
            int slot = i * 128 + tid;                // 0..511 over 64x64 tile
            int r = slot >> 3, c = (slot & 7) * 8;
            uint32_t so = (uint32_t)(r*ALDP + c) * 2;
            cp16(dst + 0*KVT_ELEMS*2 + so, &g_kh[kgbase + (size_t)(kt*64 + r)*HDIM + c]);
            cp16(dst + 1*KVT_ELEMS*2 + so, &g_kl[kgbase + (size_t)(kt*64 + r)*HDIM + c]);
            cp16(dst + 2*KVT_ELEMS*2 + so, &g_vth[vgbase + (size_t)r*SEQ + kt*64 + c]);
            cp16(dst + 3*KVT_ELEMS*2 + so, &g_vtl[vgbase + (size_t)r*SEQ + kt*64 + c]);
        }
    };

    float O[2][8][4];
#pragma unroll
    for (int i = 0; i < 2; i++)
#pragma unroll
        for (int j = 0; j < 8; j++)
#pragma unroll
            for (int q = 0; q < 4; q++) O[i][j][q] = 0.0f;
    float lacc[4] = {0.f, 0.f, 0.f, 0.f};
    float mrun[4] = {-1e30f, -1e30f, -1e30f, -1e30f};

    uint32_t qsbh = smem_u32(Qh), qsbl = smem_u32(Ql);

    load_kv(0, 0);
    CP_COMMIT();

    for (int kt = 0; kt < SEQ/64; kt++) {
        int buf = kt & 1;
        CP_WAIT0();
        __syncthreads();
        if (kt + 1 < SEQ/64) { load_kv(kt + 1, buf ^ 1); CP_COMMIT(); }

        uint32_t ksbh = kvb + (uint32_t)(buf*KVBUF_ELEMS + 0*KVT_ELEMS) * 2;
        uint32_t ksbl = kvb + (uint32_t)(buf*KVBUF_ELEMS + 1*KVT_ELEMS) * 2;
        uint32_t vsbh = kvb + (uint32_t)(buf*KVBUF_ELEMS + 2*KVT_ELEMS) * 2;
        uint32_t vsbl = kvb + (uint32_t)(buf*KVBUF_ELEMS + 3*KVT_ELEMS) * 2;

        // ---- S = Q K^T ----
        float S[2][8][4];
#pragma unroll
        for (int i = 0; i < 2; i++)
#pragma unroll
            for (int j = 0; j < 8; j++)
#pragma unroll
                for (int q = 0; q < 4; q++) S[i][j][q] = 0.0f;

#pragma unroll
        for (int ks = 0; ks < 4; ks++) {
            uint32_t qh[2][4], ql[2][4];
#pragma unroll
            for (int mi = 0; mi < 2; mi++) {
                uint32_t off = (uint32_t)((wm + mi*16 + (lane & 15)) * ALDP
                                           + ks*16 + (lane >> 4) * 8) * 2;
                ldsm_x4(qh[mi], qsbh + off);
                ldsm_x4(ql[mi], qsbl + off);
            }
#pragma unroll
            for (int nj = 0; nj < 4; nj++) {
                uint32_t boff = (uint32_t)((nj*16 + (lane & 7) + ((lane >> 4) & 1) * 8) * ALDP
                                           + ks*16 + ((lane >> 3) & 1) * 8) * 2;
                uint32_t kh[4], kl[4];
                ldsm_x4(kh, ksbh + boff);
                ldsm_x4(kl, ksbl + boff);
#pragma unroll
                for (int s2 = 0; s2 < 2; s2++) {
#pragma unroll
                    for (int mi = 0; mi < 2; mi++) {
                        float* d = S[mi][nj*2 + s2];
                        mma16816(d, qh[mi], kh[s2*2], kh[s2*2+1]);
                        mma16816(d, qh[mi], kl[s2*2], kl[s2*2+1]);
                        mma16816(d, ql[mi], kh[s2*2], kh[s2*2+1]);
                    }
                }
            }
        }

        // ---- online softmax ----
        float tmx[4] = {-1e30f, -1e30f, -1e30f, -1e30f};
#pragma unroll
        for (int mi = 0; mi < 2; mi++)
#pragma unroll
            for (int ni = 0; ni < 8; ni++) {
                tmx[mi*2+0] = fmaxf(tmx[mi*2+0], fmaxf(S[mi][ni][0], S[mi][ni][1]));
                tmx[mi*2+1] = fmaxf(tmx[mi*2+1], fmaxf(S[mi][ni][2], S[mi][ni][3]));
            }
#pragma unroll
        for (int i = 0; i < 4; i++) {
            tmx[i] = fmaxf(tmx[i], __shfl_xor_sync(0xffffffffu, tmx[i], 1));
            tmx[i] = fmaxf(tmx[i], __shfl_xor_sync(0xffffffffu, tmx[i], 2));
        }
        float corr[4];
#pragma unroll
        for (int i = 0; i < 4; i++) {
            float mn = fmaxf(mrun[i], tmx[i]);
            corr[i] = e2((mrun[i] - mn) * EXPSCALE);
            mrun[i] = mn;
            lacc[i] *= corr[i];
        }
#pragma unroll
        for (int mi = 0; mi < 2; mi++)
#pragma unroll
            for (int ni = 0; ni < 8; ni++) {
                O[mi][ni][0] *= corr[mi*2+0];
                O[mi][ni][1] *= corr[mi*2+0];
                O[mi][ni][2] *= corr[mi*2+1];
                O[mi][ni][3] *= corr[mi*2+1];
            }
#pragma unroll
        for (int mi = 0; mi < 2; mi++)
#pragma unroll
            for (int ni = 0; ni < 8; ni++) {
                float p0 = e2((S[mi][ni][0] - mrun[mi*2+0]) * EXPSCALE);
                float p1 = e2((S[mi][ni][1] - mrun[mi*2+0]) * EXPSCALE);
                float p2 = e2((S[mi][ni][2] - mrun[mi*2+1]) * EXPSCALE);
                float p3 = e2((S[mi][ni][3] - mrun[mi*2+1]) * EXPSCALE);
                S[mi][ni][0] = p0; S[mi][ni][1] = p1;
                S[mi][ni][2] = p2; S[mi][ni][3] = p3;
                lacc[mi*2+0] += p0 + p1;
                lacc[mi*2+1] += p2 + p3;
            }

        // ---- O += P @ V ----
#pragma unroll
        for (int ks = 0; ks < 4; ks++) {
            uint32_t pah[2][4], pal[2][4];
#pragma unroll
            for (int mi = 0; mi < 2; mi++) {
                pah[mi][0] = packsplit(S[mi][2*ks  ][0], S[mi][2*ks  ][1], pal[mi][0]);
                pah[mi][1] = packsplit(S[mi][2*ks  ][2], S[mi][2*ks  ][3], pal[mi][1]);
                pah[mi][2] = packsplit(S[mi][2*ks+1][0], S[mi][2*ks+1][1], pal[mi][2]);
                pah[mi][3] = packsplit(S[mi][2*ks+1][2], S[mi][2*ks+1][3], pal[mi][3]);
            }
#pragma unroll
            for (int dj = 0; dj < 4; dj++) {
                uint32_t boff = (uint32_t)((dj*16 + (lane & 7) + ((lane >> 4) & 1) * 8) * ALDP
                                           + ks*16 + ((lane >> 3) & 1) * 8) * 2;
                uint32_t vh[4], vl[4];
                ldsm_x4(vh, vsbh + boff);
                ldsm_x4(vl, vsbl + boff);
#pragma unroll
                for (int s2 = 0; s2 < 2; s2++) {
#pragma unroll
                    for (int mi = 0; mi < 2; mi++) {
                        float* d = O[mi][dj*2 + s2];
                        mma16816(d, pah[mi], vh[s2*2], vh[s2*2+1]);
                        mma16816(d, pah[mi], vl[s2*2], vl[s2*2+1]);
                        mma16816(d, pal[mi], vh[s2*2], vh[s2*2+1]);
                    }
                }
            }
        }
    }

    // ---- finalize ----
    float inv[4];
#pragma unroll
    for (int i = 0; i < 4; i++) {
        lacc[i] += __shfl_xor_sync(0xffffffffu, lacc[i], 1);
        lacc[i] += __shfl_xor_sync(0xffffffffu, lacc[i], 2);
        inv[i] = 1.0f / lacc[i];
    }
    int b = bh >> 4, h = bh & 15;
#pragma unroll
    for (int mi = 0; mi < 2; mi++) {
#pragma unroll
        for (int h2 = 0; h2 < 2; h2++) {
            int m = q0 + wm + mi*16 + (lane >> 2) + h2*8;
            float* dst = g_attn + ((size_t)b * SEQ + m) * EMB + h * HDIM;
            float iv = inv[mi*2 + h2];
#pragma unroll
            for (int ni = 0; ni < 8; ni++) {
                float2 r;
                r.x = O[mi][ni][h2*2+0] * iv;
                r.y = O[mi][ni][h2*2+1] * iv;
                *(float2*)&dst[ni*8 + 2*(lane & 3)] = r;
            }
        }
    }
}

// ---------------------------------------------------------------------------
extern "C" void kernel_launch(void* const* d_in, const int* in_sizes, int n_in,
                              void* d_out, int out_size) {
    const float* x     = (const float*)d_in[0];   // [B,T,E]
    const float* w_qkv = (const float*)d_in[1];   // [3E,E]
    const float* w_out = (const float*)d_in[2];   // [E,E]
    float* out = (float*)d_out;                   // [B,T,E]

    float* gattn;
    cudaGetSymbolAddress((void**)&gattn, g_attn);

    cudaFuncSetAttribute(hmma_gemm<0>, cudaFuncAttributeMaxDynamicSharedMemorySize, GEMM_SMEM);
    cudaFuncSetAttribute(hmma_gemm<1>, cudaFuncAttributeMaxDynamicSharedMemorySize, GEMM_SMEM);
    cudaFuncSetAttribute(attn_hmma,    cudaFuncAttributeMaxDynamicSharedMemorySize, ATT_SMEM);

    // 1) QKV projection (pair-major n-tiling, coalesced head-split epilogue)
    hmma_gemm<0><<<dim3(NQKV/128, MROWS/128), 512, GEMM_SMEM>>>(x, w_qkv, nullptr);

    // 2) HMMA flash attention -> fp32 g_attn
    attn_hmma<<<dim3(SEQ/128, BATCH*HEADS), 128, ATT_SMEM>>>();

    // 3) output projection
    hmma_gemm<1><<<dim3(EMB/128, MROWS/128), 512, GEMM_SMEM>>>(gattn, w_out, out);
}